// round 10
// baseline (speedup 1.0000x reference)
#include <cuda_runtime.h>
#include <cuda_fp16.h>
#include <math.h>
#include <stdint.h>

// Problem constants
#define TT 70
#define BB 128
#define EE 400
#define HH 1150
#define VV 33278

// Padded dims (K multiples of 32, strides 16B-aligned)
#define KP_E 416
#define KP_H 1152
#define N4P_H 4608
#define N4P_E 1664

// ---------------------------------------------------------------------------
// Scratch (device globals)
// ---------------------------------------------------------------------------
__device__ __half g_x0  [TT * BB * KP_E];
__device__ __half g_x1  [TT * BB * KP_H];
__device__ __half g_x2  [TT * BB * KP_H];
__device__ __half g_x3  [TT * BB * KP_E];
__device__ __half g_embf[VV * KP_E];
__device__ __half g_Wih [N4P_H * KP_H];
__device__ __half g_Whh [N4P_H * KP_H];
__device__ float  g_bias[N4P_H];
__device__ float  g_xproj[TT * BB * N4P_H];
__device__ float  g_c   [2 * BB * HH];
__device__ __half g_h0f [BB * KP_H];
__device__ unsigned g_count;            // grid barrier arrival counter
__device__ volatile unsigned g_gen;     // grid barrier generation

// ---------------------------------------------------------------------------
// PTX helpers
// ---------------------------------------------------------------------------
__device__ __forceinline__ void cp16(unsigned s, const void* g) {
    asm volatile("cp.async.cg.shared.global [%0], [%1], 16;" :: "r"(s), "l"(g));
}
__device__ __forceinline__ void cp16z(unsigned s, const void* g, int sz) {
    asm volatile("cp.async.cg.shared.global [%0], [%1], 16, %2;" :: "r"(s), "l"(g), "r"(sz));
}
__device__ __forceinline__ void cp_commit() {
    asm volatile("cp.async.commit_group;");
}
__device__ __forceinline__ void mma_f16(float c[4], unsigned a0, unsigned a1,
                                        unsigned a2, unsigned a3,
                                        unsigned b0, unsigned b1)
{
    asm("mma.sync.aligned.m16n8k16.row.col.f32.f16.f16.f32 "
        "{%0,%1,%2,%3},{%4,%5,%6,%7},{%8,%9},{%0,%1,%2,%3};"
        : "+f"(c[0]), "+f"(c[1]), "+f"(c[2]), "+f"(c[3])
        : "r"(a0), "r"(a1), "r"(a2), "r"(a3), "r"(b0), "r"(b1));
}
__device__ __forceinline__ void ldsm_x4(unsigned& r0, unsigned& r1,
                                        unsigned& r2, unsigned& r3, uint32_t a)
{
    asm volatile("ldmatrix.sync.aligned.m8n8.x4.shared.b16 {%0,%1,%2,%3}, [%4];"
                 : "=r"(r0), "=r"(r1), "=r"(r2), "=r"(r3) : "r"(a));
}
__device__ __forceinline__ float fsigmoid(float x) {
    return 1.0f / (1.0f + __expf(-x));
}
__device__ __forceinline__ float ftanh(float x) {
    return 2.0f / (1.0f + __expf(-2.0f * x)) - 1.0f;
}

// Grid-wide barrier (all blocks co-resident by construction)
__device__ __forceinline__ void grid_bar(unsigned nblocks) {
    __syncthreads();
    if (threadIdx.x == 0) {
        unsigned old = g_gen;
        __threadfence();
        unsigned t = atomicAdd(&g_count, 1u);
        if (t == nblocks - 1u) {
            g_count = 0u;
            __threadfence();
            g_gen = old + 1u;
        } else {
            while (g_gen == old) { }
        }
        __threadfence();
    }
    __syncthreads();
}

// ---------------------------------------------------------------------------
// Preprocessing kernels
// ---------------------------------------------------------------------------
__global__ void zero_half(__half* p, int n4) {
    uint4 z = {0, 0, 0, 0};
    for (int i = blockIdx.x * blockDim.x + threadIdx.x; i < n4; i += gridDim.x * blockDim.x)
        reinterpret_cast<uint4*>(p)[i] = z;
}

__global__ void embed_f16(const int* __restrict__ tokens,
                          const float* __restrict__ emb,
                          __half* __restrict__ out)
{
    int tb = blockIdx.x;
    int tok = tokens[tb];
    const float* src = emb + (size_t)tok * EE;
    __half* dst = out + (size_t)tb * KP_E;
    for (int e = threadIdx.x; e < KP_E; e += blockDim.x)
        dst[e] = (e < EE) ? __float2half(src[e]) : __half(0.0f);
}

__global__ void conv_emb(const float* __restrict__ emb, __half* __restrict__ out)
{
    int row = blockIdx.x;
    const float* src = emb + (size_t)row * EE;
    __half* dst = out + (size_t)row * KP_E;
    for (int e = threadIdx.x; e < KP_E; e += blockDim.x)
        dst[e] = (e < EE) ? __float2half(src[e]) : __half(0.0f);
}

__global__ void reorder_f16(const float* __restrict__ W, __half* __restrict__ Wr,
                            int nh, int K, int Kp)
{
    int row = blockIdx.x;
    int j = row >> 2, g = row & 3;
    bool valid = (row < 4 * nh);
    const float* src = W + (size_t)(g * nh + j) * K;
    __half* dst = Wr + (size_t)row * Kp;
    for (int k = threadIdx.x; k < Kp; k += blockDim.x)
        dst[k] = (valid && k < K) ? __float2half(src[k]) : __half(0.0f);
}

__global__ void combine_bias(const float* __restrict__ b1, const float* __restrict__ b2,
                             float* __restrict__ br, int nh, int N4p)
{
    int r = blockIdx.x * blockDim.x + threadIdx.x;
    if (r < N4p) {
        int j = r >> 2, g = r & 3;
        br[r] = (r < 4 * nh) ? b1[g * nh + j] + b2[g * nh + j] : 0.0f;
    }
}

__global__ void conv_h0(const float* __restrict__ h0, __half* __restrict__ out,
                        int nh, int Kp)
{
    int b = blockIdx.x;
    for (int k = threadIdx.x; k < Kp; k += blockDim.x)
        out[(size_t)b * Kp + k] = (k < nh) ? __float2half(h0[(size_t)b * nh + k])
                                           : __half(0.0f);
}

// ---------------------------------------------------------------------------
// FP16 GEMM (NT), 3-stage cp.async pipeline + ldmatrix; FAT warp tiles.
// C[m,n] = sum_k A[m,k]*B[n,k] + bias[n]
// Block 256x128, BK=32, 256 threads = 8 warps (4m x 2n), warp tile 64x64.
// M must be a multiple of 256 (8960 = 35*256). smem: 3*(20480+10240)=92160 B.
// ---------------------------------------------------------------------------
__global__ void __launch_bounds__(256) gemm_f16(
    const __half* __restrict__ A, const __half* __restrict__ B,
    const float* __restrict__ bias, float* __restrict__ C,
    int N, int Kp, int lda, int ldb, int ldc)
{
    extern __shared__ __align__(16) char dsm[];
    unsigned sA = (unsigned)__cvta_generic_to_shared(dsm);            // 3 x 20480 B
    unsigned sB = sA + 61440u;                                        // 3 x 10240 B

    int tid  = threadIdx.x;
    int warp = tid >> 5, lane = tid & 31;
    int wm = warp >> 1, wn = warp & 1;
    int g  = lane >> 2, tg = lane & 3;
    int m0 = blockIdx.y * 256;
    int n0 = blockIdx.x * 128;

    // ldmatrix lane offsets
    int a_row = (lane & 7) + ((lane >> 3) & 1) * 8;
    int a_col = (lane >> 4) * 8;
    int b_row = (lane & 7) + (lane >> 4) * 8;
    int b_col = ((lane >> 3) & 1) * 8;

    float acc[4][8][4] = {};
    int nk = Kp >> 5;     // >= 13 always

#define ISSUE_AB(grp, stage) do {                                              \
        int _kt = (grp) << 5;                                                  \
        unsigned _sa = sA + (unsigned)(stage) * 20480u;                        \
        unsigned _sb = sB + (unsigned)(stage) * 10240u;                        \
        _Pragma("unroll")                                                      \
        for (int s = 0; s < 4; s++) {                                          \
            int c = tid + s * 256;                                             \
            int row = c >> 2, ko = (c & 3) * 8;                                \
            cp16(_sa + (unsigned)((row * 40 + ko) * 2),                        \
                 A + (size_t)(m0 + row) * lda + _kt + ko);                     \
        }                                                                      \
        _Pragma("unroll")                                                      \
        for (int s = 0; s < 2; s++) {                                          \
            int c = tid + s * 256;                                             \
            int row = c >> 2, ko = (c & 3) * 8;                                \
            int gn = n0 + row;                                                 \
            int sz = (gn < N) ? 16 : 0;                                        \
            const __half* gb = B + (size_t)(gn < N ? gn : 0) * ldb + _kt + ko; \
            cp16z(_sb + (unsigned)((row * 40 + ko) * 2), gb, sz);              \
        }                                                                      \
        cp_commit();                                                           \
    } while (0)

    ISSUE_AB(0, 0);
    ISSUE_AB(1, 1);

    for (int it = 0; it < nk; it++) {
        if (it + 2 <= nk) asm volatile("cp.async.wait_group 1;");
        else              asm volatile("cp.async.wait_group 0;");
        __syncthreads();
        if (it + 2 < nk) { int st = (it + 2) % 3; ISSUE_AB(it + 2, st); }

        unsigned ab = sA + (unsigned)(it % 3) * 20480u;
        unsigned bb = sB + (unsigned)(it % 3) * 10240u;
        #pragma unroll
        for (int kk = 0; kk < 32; kk += 16) {
            unsigned af[4][4], bf[8][2];
            #pragma unroll
            for (int i = 0; i < 4; i++) {
                int ar = wm * 64 + i * 16;
                ldsm_x4(af[i][0], af[i][1], af[i][2], af[i][3],
                        ab + (unsigned)(((ar + a_row) * 40 + kk + a_col) * 2));
            }
            #pragma unroll
            for (int j = 0; j < 8; j += 2) {
                int br = wn * 64 + j * 8;
                ldsm_x4(bf[j][0], bf[j][1], bf[j + 1][0], bf[j + 1][1],
                        bb + (unsigned)(((br + b_row) * 40 + kk + b_col) * 2));
            }
            #pragma unroll
            for (int i = 0; i < 4; i++)
                #pragma unroll
                for (int j = 0; j < 8; j++)
                    mma_f16(acc[i][j], af[i][0], af[i][1], af[i][2], af[i][3],
                            bf[j][0], bf[j][1]);
        }
    }
#undef ISSUE_AB

    #pragma unroll
    for (int i = 0; i < 4; i++) {
        int r0 = m0 + wm * 64 + i * 16 + g;
        #pragma unroll
        for (int j = 0; j < 8; j++) {
            int col = n0 + wn * 64 + j * 8 + 2 * tg;
            if (col < N) {
                float bz  = bias ? bias[col] : 0.0f;
                float bz1 = bias ? bias[col + 1] : 0.0f;
                float2 v0 = {acc[i][j][0] + bz, acc[i][j][1] + bz1};
                float2 v1 = {acc[i][j][2] + bz, acc[i][j][3] + bz1};
                *reinterpret_cast<float2*>(C + (size_t)r0 * ldc + col) = v0;
                *reinterpret_cast<float2*>(C + (size_t)(r0 + 8) * ldc + col) = v1;
            }
        }
    }
}

// ---------------------------------------------------------------------------
// Persistent LSTM recurrence: one launch per layer, all 70 timesteps.
// W slice resident in smem; h streamed per step (6-stage cp.async);
// grid barrier between steps; ldmatrix operand fetch.
// ---------------------------------------------------------------------------
__global__ void __launch_bounds__(256) lstm_persist(
    const __half* __restrict__ h0f,
    const float*  __restrict__ c0,
    const __half* __restrict__ Wg,
    const float*  __restrict__ xproj,
    float* __restrict__ cbuf,
    __half* __restrict__ xout,
    int nh, int Kp, int N4p, int pitch, unsigned nblocks)
{
    extern __shared__ __align__(16) char dsm[];
    __half* Ws   = (__half*)dsm;
    __half* Hs   = Ws + 64 * pitch;
    float*  gates = (float*)(Hs + 6 * 2560);

    int tid  = threadIdx.x;
    int warp = tid >> 5, lane = tid & 31;
    int wm = warp & 1, wn = warp >> 1;
    int n0 = blockIdx.x * 64;
    int b0 = blockIdx.y * 64;

    unsigned sW = (unsigned)__cvta_generic_to_shared(Ws);
    unsigned sH = (unsigned)__cvta_generic_to_shared(Hs);

    // ldmatrix lane offsets
    int a_row = (lane & 7) + ((lane >> 3) & 1) * 8;
    int a_col = (lane >> 4) * 8;
    int b_row = (lane & 7) + (lane >> 4) * 8;
    int b_col = ((lane >> 3) & 1) * 8;

    int kch = Kp >> 3;
    for (int c = tid; c < 64 * kch; c += 256) {
        int row = c / kch;
        int kc  = (c - row * kch) << 3;
        cp16(sW + (unsigned)(row * pitch + kc) * 2, Wg + (size_t)(n0 + row) * Kp + kc);
    }
    cp_commit();
    asm volatile("cp.async.wait_group 0;");
    __syncthreads();

    int nk   = Kp >> 5;
    int crow = tid >> 2;
    int cko  = (tid & 3) * 8;
    int jbase = n0 >> 2;

    for (int t = 0; t < TT; t++) {
        const __half* hsrc = t ? xout + (size_t)(t - 1) * BB * Kp : h0f;
        const float*  cin  = t ? cbuf + (size_t)((t - 1) & 1) * BB * HH : c0;
        float*  cout = cbuf + (size_t)(t & 1) * BB * HH;
        __half* yout = xout + (size_t)t * BB * Kp;
        const float* xp = xproj + (size_t)t * BB * N4p;

        float acc[2][2][4] = {};

#define ISSUE_H(grp, stage) do {                                           \
        cp16(sH + (unsigned)(stage) * 5120u + (crow * 40 + cko) * 2,       \
             hsrc + (size_t)(b0 + crow) * Kp + ((grp) << 5) + cko);        \
        cp_commit();                                                       \
    } while (0)

        ISSUE_H(0, 0); ISSUE_H(1, 1); ISSUE_H(2, 2);
        ISSUE_H(3, 3); ISSUE_H(4, 4);

        for (int it = 0; it < nk; it++) {
            if (it + 5 <= nk) asm volatile("cp.async.wait_group 4;");
            else              asm volatile("cp.async.wait_group 0;");
            __syncthreads();
            if (it + 5 < nk) { int st = (it + 5) % 6; ISSUE_H(it + 5, st); }

            unsigned ab = sH + (unsigned)(it % 6) * 5120u;
            int k0 = it << 5;
            #pragma unroll
            for (int kk = 0; kk < 32; kk += 16) {
                unsigned af[2][4], bf[2][2];
                #pragma unroll
                for (int i = 0; i < 2; i++) {
                    int ar = wm * 32 + i * 16;
                    ldsm_x4(af[i][0], af[i][1], af[i][2], af[i][3],
                            ab + (unsigned)(((ar + a_row) * 40 + kk + a_col) * 2));
                }
                {
                    int br = wn * 16;
                    ldsm_x4(bf[0][0], bf[0][1], bf[1][0], bf[1][1],
                            sW + (unsigned)(((br + b_row) * pitch + k0 + kk + b_col) * 2));
                }
                #pragma unroll
                for (int i = 0; i < 2; i++)
                    #pragma unroll
                    for (int j = 0; j < 2; j++)
                        mma_f16(acc[i][j], af[i][0], af[i][1], af[i][2], af[i][3],
                                bf[j][0], bf[j][1]);
            }
        }
#undef ISSUE_H

        int g  = lane >> 2, tg = lane & 3;
        #pragma unroll
        for (int i = 0; i < 2; i++) {
            int r0 = wm * 32 + i * 16 + g;
            #pragma unroll
            for (int j = 0; j < 2; j++) {
                int col = wn * 16 + j * 8 + 2 * tg;
                gates[r0 * 65 + col]           = acc[i][j][0];
                gates[r0 * 65 + col + 1]       = acc[i][j][1];
                gates[(r0 + 8) * 65 + col]     = acc[i][j][2];
                gates[(r0 + 8) * 65 + col + 1] = acc[i][j][3];
            }
        }
        __syncthreads();

        #pragma unroll
        for (int p = tid; p < 1024; p += 256) {
            int b  = p >> 4;
            int jl = p & 15;
            int j  = jbase + jl;
            if (j < nh) {
                int bg = b0 + b;
                const float4 xv = *reinterpret_cast<const float4*>(
                    xp + (size_t)bg * N4p + n0 + jl * 4);
                float gi = gates[b * 65 + jl * 4 + 0] + xv.x;
                float gf = gates[b * 65 + jl * 4 + 1] + xv.y;
                float gg = gates[b * 65 + jl * 4 + 2] + xv.z;
                float go = gates[b * 65 + jl * 4 + 3] + xv.w;
                float iv = fsigmoid(gi);
                float fv = fsigmoid(gf);
                float gv = ftanh(gg);
                float ov = fsigmoid(go);
                float cv = fv * cin[(size_t)bg * nh + j] + iv * gv;
                float hv = ov * ftanh(cv);
                cout[(size_t)bg * nh + j] = cv;
                yout[(size_t)bg * Kp + j] = __float2half(hv);
            }
        }

        if (t + 1 < TT) grid_bar(nblocks);
    }
}

// ---------------------------------------------------------------------------
// Layer driver
// ---------------------------------------------------------------------------
static void run_layer(const __half* x_in, int Kp_in, int K_in, int nh, int Kp_h,
                      int N4p,
                      const float* W_ih, const float* W_hh,
                      const float* b_ih, const float* b_hh,
                      const float* h0, const float* c0,
                      __half* x_out,
                      __half* Wih, __half* Whh, float* bias,
                      float* xproj, float* cbuf, __half* h0f)
{
    reorder_f16<<<N4p, 256>>>(W_ih, Wih, nh, K_in, Kp_in);
    reorder_f16<<<N4p, 256>>>(W_hh, Whh, nh, nh, Kp_h);
    combine_bias<<<(N4p + 255) / 256, 256>>>(b_ih, b_hh, bias, nh, N4p);
    conv_h0<<<BB, 256>>>(h0, h0f, nh, Kp_h);

    // Input projection: xproj = x_in @ Wih^T + bias
    {
        dim3 grid(N4p / 128, (TT * BB) / 256);
        gemm_f16<<<grid, 256, 92160>>>(x_in, Wih, bias, xproj, N4p, Kp_in,
                                       Kp_in, Kp_in, N4p);
    }

    // Persistent recurrence: single launch for all 70 steps
    {
        int pitch = Kp_h + 8;
        size_t smem = (size_t)64 * pitch * 2 + 6 * 2560 * 2 + 64 * 65 * 4;
        dim3 grid(N4p / 64, 2);
        unsigned nblocks = (N4p / 64) * 2;
        lstm_persist<<<grid, 256, smem>>>(h0f, c0, Whh, xproj, cbuf, x_out,
                                          nh, Kp_h, N4p, pitch, nblocks);
    }
}

extern "C" void kernel_launch(void* const* d_in, const int* in_sizes, int n_in,
                              void* d_out, int out_size)
{
    const int*   tokens = (const int*)  d_in[0];
    const float* h0_0   = (const float*)d_in[1];
    const float* c0_0   = (const float*)d_in[2];
    const float* h0_1   = (const float*)d_in[3];
    const float* c0_1   = (const float*)d_in[4];
    const float* h0_2   = (const float*)d_in[5];
    const float* c0_2   = (const float*)d_in[6];
    const float* embw   = (const float*)d_in[7];
    const float* W_ih0  = (const float*)d_in[8];
    const float* W_hh0  = (const float*)d_in[9];
    const float* b_ih0  = (const float*)d_in[10];
    const float* b_hh0  = (const float*)d_in[11];
    const float* W_ih1  = (const float*)d_in[12];
    const float* W_hh1  = (const float*)d_in[13];
    const float* b_ih1  = (const float*)d_in[14];
    const float* b_hh1  = (const float*)d_in[15];
    const float* W_ih2  = (const float*)d_in[16];
    const float* W_hh2  = (const float*)d_in[17];
    const float* b_ih2  = (const float*)d_in[18];
    const float* b_hh2  = (const float*)d_in[19];
    const float* dec_b  = (const float*)d_in[20];
    float* logits = (float*)d_out;

    __half *x0, *x1, *x2, *x3, *embf, *Wih, *Whh, *h0f;
    float *bias, *xproj, *cbuf;
    cudaGetSymbolAddress((void**)&x0,    g_x0);
    cudaGetSymbolAddress((void**)&x1,    g_x1);
    cudaGetSymbolAddress((void**)&x2,    g_x2);
    cudaGetSymbolAddress((void**)&x3,    g_x3);
    cudaGetSymbolAddress((void**)&embf,  g_embf);
    cudaGetSymbolAddress((void**)&Wih,   g_Wih);
    cudaGetSymbolAddress((void**)&Whh,   g_Whh);
    cudaGetSymbolAddress((void**)&bias,  g_bias);
    cudaGetSymbolAddress((void**)&xproj, g_xproj);
    cudaGetSymbolAddress((void**)&cbuf,  g_c);
    cudaGetSymbolAddress((void**)&h0f,   g_h0f);

    cudaFuncSetAttribute(gemm_f16, cudaFuncAttributeMaxDynamicSharedMemorySize,
                         92160);
    cudaFuncSetAttribute(lstm_persist, cudaFuncAttributeMaxDynamicSharedMemorySize,
                         64 * (KP_H + 8) * 2 + 6 * 2560 * 2 + 64 * 65 * 4);

    // Zero pad columns of activation buffers
    zero_half<<<512, 256>>>(x1, TT * BB * KP_H / 8);
    zero_half<<<512, 256>>>(x2, TT * BB * KP_H / 8);
    zero_half<<<512, 256>>>(x3, TT * BB * KP_E / 8);

    // Preprocess: embedding gather + fp16 embedding table
    embed_f16<<<TT * BB, 256>>>(tokens, embw, x0);
    conv_emb<<<VV, 128>>>(embw, embf);

    // Three LSTM layers
    run_layer(x0, KP_E, EE, HH, KP_H, N4P_H, W_ih0, W_hh0, b_ih0, b_hh0,
              h0_0, c0_0, x1, Wih, Whh, bias, xproj, cbuf, h0f);
    run_layer(x1, KP_H, HH, HH, KP_H, N4P_H, W_ih1, W_hh1, b_ih1, b_hh1,
              h0_1, c0_1, x2, Wih, Whh, bias, xproj, cbuf, h0f);
    run_layer(x2, KP_H, HH, EE, KP_E, N4P_E, W_ih2, W_hh2, b_ih2, b_hh2,
              h0_2, c0_2, x3, Wih, Whh, bias, xproj, cbuf, h0f);

    // Tied decoder: logits = x3 @ embf^T + dec_b
    {
        dim3 grid((VV + 127) / 128, (TT * BB) / 256);
        gemm_f16<<<grid, 256, 92160>>>(x3, embf, dec_b, logits, VV, KP_E,
                                       KP_E, KP_E, VV);
    }
}

// round 11
// speedup vs baseline: 1.1836x; 1.1836x over previous
#include <cuda_runtime.h>
#include <cuda_fp16.h>
#include <math.h>
#include <stdint.h>

// Problem constants
#define TT 70
#define BB 128
#define EE 400
#define HH 1150
#define VV 33278

// Padded dims (K multiples of 32, strides 16B-aligned)
#define KP_E 416
#define KP_H 1152
#define N4P_H 4608
#define N4P_E 1664

// ---------------------------------------------------------------------------
// Scratch (device globals; zero-initialized at module load — pad columns of
// activation buffers are NEVER written non-zero, so no runtime zeroing needed)
// ---------------------------------------------------------------------------
__device__ __half g_x0  [TT * BB * KP_E];
__device__ __half g_x1  [TT * BB * KP_H];
__device__ __half g_x2  [TT * BB * KP_H];
__device__ __half g_x3  [TT * BB * KP_E];
__device__ __half g_embf[VV * KP_E];
__device__ __half g_Wih [N4P_H * KP_H];
__device__ __half g_Whh [N4P_H * KP_H];
__device__ float  g_bias[N4P_H];
__device__ float  g_xproj[TT * BB * N4P_H];
__device__ float  g_c   [2 * BB * HH];
__device__ __half g_h0f [BB * KP_H];
__device__ unsigned g_count;            // grid barrier arrival counter
__device__ volatile unsigned g_gen;     // grid barrier generation

// ---------------------------------------------------------------------------
// PTX helpers
// ---------------------------------------------------------------------------
__device__ __forceinline__ void cp16(unsigned s, const void* g) {
    asm volatile("cp.async.cg.shared.global [%0], [%1], 16;" :: "r"(s), "l"(g));
}
__device__ __forceinline__ void cp16z(unsigned s, const void* g, int sz) {
    asm volatile("cp.async.cg.shared.global [%0], [%1], 16, %2;" :: "r"(s), "l"(g), "r"(sz));
}
__device__ __forceinline__ void cp_commit() {
    asm volatile("cp.async.commit_group;");
}
__device__ __forceinline__ void mma_f16(float c[4], unsigned a0, unsigned a1,
                                        unsigned a2, unsigned a3,
                                        unsigned b0, unsigned b1)
{
    asm("mma.sync.aligned.m16n8k16.row.col.f32.f16.f16.f32 "
        "{%0,%1,%2,%3},{%4,%5,%6,%7},{%8,%9},{%0,%1,%2,%3};"
        : "+f"(c[0]), "+f"(c[1]), "+f"(c[2]), "+f"(c[3])
        : "r"(a0), "r"(a1), "r"(a2), "r"(a3), "r"(b0), "r"(b1));
}
__device__ __forceinline__ void ldsm_x4(unsigned& r0, unsigned& r1,
                                        unsigned& r2, unsigned& r3, uint32_t a)
{
    asm volatile("ldmatrix.sync.aligned.m8n8.x4.shared.b16 {%0,%1,%2,%3}, [%4];"
                 : "=r"(r0), "=r"(r1), "=r"(r2), "=r"(r3) : "r"(a));
}
__device__ __forceinline__ float fsigmoid(float x) {
    return 1.0f / (1.0f + __expf(-x));
}
__device__ __forceinline__ float ftanh(float x) {
    return 2.0f / (1.0f + __expf(-2.0f * x)) - 1.0f;
}

// Grid-wide barrier (all blocks co-resident by construction)
__device__ __forceinline__ void grid_bar(unsigned nblocks) {
    __syncthreads();
    if (threadIdx.x == 0) {
        unsigned old = g_gen;
        __threadfence();
        unsigned t = atomicAdd(&g_count, 1u);
        if (t == nblocks - 1u) {
            g_count = 0u;
            __threadfence();
            g_gen = old + 1u;
        } else {
            while (g_gen == old) { }
        }
        __threadfence();
    }
    __syncthreads();
}

// ---------------------------------------------------------------------------
// Preprocessing kernels
// ---------------------------------------------------------------------------
__global__ void embed_f16(const int* __restrict__ tokens,
                          const float* __restrict__ emb,
                          __half* __restrict__ out)
{
    int tb = blockIdx.x;
    int tok = tokens[tb];
    const float* src = emb + (size_t)tok * EE;
    __half* dst = out + (size_t)tb * KP_E;
    for (int e = threadIdx.x; e < KP_E; e += blockDim.x)
        dst[e] = (e < EE) ? __float2half(src[e]) : __half(0.0f);
}

__global__ void conv_emb(const float* __restrict__ emb, __half* __restrict__ out)
{
    int row = blockIdx.x;
    const float* src = emb + (size_t)row * EE;
    __half* dst = out + (size_t)row * KP_E;
    for (int e = threadIdx.x; e < KP_E; e += blockDim.x)
        dst[e] = (e < EE) ? __float2half(src[e]) : __half(0.0f);
}

__global__ void reorder_f16(const float* __restrict__ W, __half* __restrict__ Wr,
                            int nh, int K, int Kp)
{
    int row = blockIdx.x;
    int j = row >> 2, g = row & 3;
    bool valid = (row < 4 * nh);
    const float* src = W + (size_t)(g * nh + j) * K;
    __half* dst = Wr + (size_t)row * Kp;
    for (int k = threadIdx.x; k < Kp; k += blockDim.x)
        dst[k] = (valid && k < K) ? __float2half(src[k]) : __half(0.0f);
}

__global__ void combine_bias(const float* __restrict__ b1, const float* __restrict__ b2,
                             float* __restrict__ br, int nh, int N4p)
{
    int r = blockIdx.x * blockDim.x + threadIdx.x;
    if (r < N4p) {
        int j = r >> 2, g = r & 3;
        br[r] = (r < 4 * nh) ? b1[g * nh + j] + b2[g * nh + j] : 0.0f;
    }
}

__global__ void conv_h0(const float* __restrict__ h0, __half* __restrict__ out,
                        int nh, int Kp)
{
    int b = blockIdx.x;
    for (int k = threadIdx.x; k < Kp; k += blockDim.x)
        out[(size_t)b * Kp + k] = (k < nh) ? __float2half(h0[(size_t)b * nh + k])
                                           : __half(0.0f);
}

// ---------------------------------------------------------------------------
// FP16 GEMM (NT), 3-stage cp.async pipeline + ldmatrix operand fetch.
// C[m,n] = sum_k A[m,k]*B[n,k] + bias[n]
// Block 128x128, BK=32, 256 threads (8 warps 2m x 4n), warp tile 64x32.
// ---------------------------------------------------------------------------
__global__ void __launch_bounds__(256) gemm_f16(
    const __half* __restrict__ A, const __half* __restrict__ B,
    const float* __restrict__ bias, float* __restrict__ C,
    int N, int Kp, int lda, int ldb, int ldc)
{
    extern __shared__ __align__(16) char dsm[];
    __half* Asm = (__half*)dsm;              // 3 stages x 5120 halfs
    __half* Bsm = Asm + 3 * 5120;            // 3 stages x 5120 halfs

    int tid  = threadIdx.x;
    int warp = tid >> 5, lane = tid & 31;
    int wm = warp & 1, wn = warp >> 1;
    int g  = lane >> 2, tg = lane & 3;
    int m0 = blockIdx.y * 128;
    int n0 = blockIdx.x * 128;

    unsigned sA = (unsigned)__cvta_generic_to_shared(Asm);
    unsigned sB = (unsigned)__cvta_generic_to_shared(Bsm);

    // ldmatrix lane offsets
    int a_row = (lane & 7) + ((lane >> 3) & 1) * 8;
    int a_col = (lane >> 4) * 8;
    int b_row = (lane & 7) + (lane >> 4) * 8;
    int b_col = ((lane >> 3) & 1) * 8;

    int crow[2], cko[2];
    #pragma unroll
    for (int s = 0; s < 2; s++) {
        int c = tid + s * 256;
        crow[s] = c >> 2;
        cko[s]  = (c & 3) * 8;
    }

    float acc[4][4][4] = {};
    int nk = Kp >> 5;     // >= 13 always

#define ISSUE_AB(grp, stage) do {                                              \
        int _kt = (grp) << 5;                                                  \
        unsigned _so = (unsigned)(stage) * 10240u;                             \
        _Pragma("unroll")                                                      \
        for (int s = 0; s < 2; s++) {                                          \
            int row = crow[s], ko = cko[s];                                    \
            cp16(sA + _so + (row * 40 + ko) * 2,                               \
                 A + (size_t)(m0 + row) * lda + _kt + ko);                     \
            int gn = n0 + row;                                                 \
            int sz = (gn < N) ? 16 : 0;                                        \
            const __half* gb = B + (size_t)(gn < N ? gn : 0) * ldb + _kt + ko; \
            cp16z(sB + _so + (row * 40 + ko) * 2, gb, sz);                     \
        }                                                                      \
        cp_commit();                                                           \
    } while (0)

    ISSUE_AB(0, 0);
    ISSUE_AB(1, 1);

    for (int it = 0; it < nk; it++) {
        if (it + 2 <= nk) asm volatile("cp.async.wait_group 1;");
        else              asm volatile("cp.async.wait_group 0;");
        __syncthreads();
        if (it + 2 < nk) { int st = (it + 2) % 3; ISSUE_AB(it + 2, st); }

        unsigned ab = sA + (unsigned)(it % 3) * 10240u;
        unsigned bb = sB + (unsigned)(it % 3) * 10240u;
        #pragma unroll
        for (int kk = 0; kk < 32; kk += 16) {
            unsigned af[4][4], bf[4][2];
            #pragma unroll
            for (int i = 0; i < 4; i++) {
                int ar = wm * 64 + i * 16;
                ldsm_x4(af[i][0], af[i][1], af[i][2], af[i][3],
                        ab + (unsigned)(((ar + a_row) * 40 + kk + a_col) * 2));
            }
            #pragma unroll
            for (int j = 0; j < 4; j += 2) {
                int br = wn * 32 + j * 8;
                ldsm_x4(bf[j][0], bf[j][1], bf[j + 1][0], bf[j + 1][1],
                        bb + (unsigned)(((br + b_row) * 40 + kk + b_col) * 2));
            }
            #pragma unroll
            for (int i = 0; i < 4; i++)
                #pragma unroll
                for (int j = 0; j < 4; j++)
                    mma_f16(acc[i][j], af[i][0], af[i][1], af[i][2], af[i][3],
                            bf[j][0], bf[j][1]);
        }
    }
#undef ISSUE_AB

    #pragma unroll
    for (int i = 0; i < 4; i++) {
        int r0 = m0 + wm * 64 + i * 16 + g;
        #pragma unroll
        for (int j = 0; j < 4; j++) {
            int col = n0 + wn * 32 + j * 8 + 2 * tg;
            if (col < N) {
                float bz  = bias ? bias[col] : 0.0f;
                float bz1 = bias ? bias[col + 1] : 0.0f;
                float2 v0 = {acc[i][j][0] + bz, acc[i][j][1] + bz1};
                float2 v1 = {acc[i][j][2] + bz, acc[i][j][3] + bz1};
                *reinterpret_cast<float2*>(C + (size_t)r0 * ldc + col) = v0;
                *reinterpret_cast<float2*>(C + (size_t)(r0 + 8) * ldc + col) = v1;
            }
        }
    }
}

// ---------------------------------------------------------------------------
// Persistent LSTM recurrence, templated on gate-column tile NTILE (64 or 32).
// NTILE=64: 8 warps as 2m x 4n (warp 32x16). NTILE=32: 4m x 2n (warp 16x16).
// W slice resident in smem; h streamed per step (6-stage cp.async);
// xp prefetched into registers at step start; grid barrier between steps.
// ---------------------------------------------------------------------------
template<int NTILE>
__global__ void __launch_bounds__(256) lstm_persist(
    const __half* __restrict__ h0f,
    const float*  __restrict__ c0,
    const __half* __restrict__ Wg,
    const float*  __restrict__ xproj,
    float* __restrict__ cbuf,
    __half* __restrict__ xout,
    int nh, int Kp, int N4p, int pitch, unsigned nblocks)
{
    constexpr int IM   = (NTILE == 64) ? 2 : 1;       // m-frags per warp
    constexpr int MW   = 16 * IM;                     // rows per m-warp
    constexpr int NPF  = NTILE / 16;                  // pointwise iters (4 or 2)
    constexpr int JL_M = NTILE / 4 - 1;               // jl mask
    constexpr int B_SH = (NTILE == 64) ? 4 : 3;       // b shift

    extern __shared__ __align__(16) char dsm[];
    __half* Ws   = (__half*)dsm;                      // NTILE x pitch
    __half* Hs   = Ws + NTILE * pitch;                // 6 stages x 2560
    float*  gates = (float*)(Hs + 6 * 2560);          // 64 x (NTILE+1)

    int tid  = threadIdx.x;
    int warp = tid >> 5, lane = tid & 31;
    int wm = (NTILE == 64) ? (warp & 1) : (warp >> 1);
    int wn = (NTILE == 64) ? (warp >> 1) : (warp & 1);
    int n0 = blockIdx.x * NTILE;
    int b0 = blockIdx.y * 64;

    unsigned sW = (unsigned)__cvta_generic_to_shared(Ws);
    unsigned sH = (unsigned)__cvta_generic_to_shared(Hs);

    // ldmatrix lane offsets
    int a_row = (lane & 7) + ((lane >> 3) & 1) * 8;
    int a_col = (lane >> 4) * 8;
    int b_row = (lane & 7) + (lane >> 4) * 8;
    int b_col = ((lane >> 3) & 1) * 8;

    int kch = Kp >> 3;
    for (int c = tid; c < NTILE * kch; c += 256) {
        int row = c / kch;
        int kc  = (c - row * kch) << 3;
        cp16(sW + (unsigned)(row * pitch + kc) * 2, Wg + (size_t)(n0 + row) * Kp + kc);
    }
    cp_commit();
    asm volatile("cp.async.wait_group 0;");
    __syncthreads();

    int nk   = Kp >> 5;
    int crow = tid >> 2;
    int cko  = (tid & 3) * 8;
    int jbase = n0 >> 2;

    for (int t = 0; t < TT; t++) {
        const __half* hsrc = t ? xout + (size_t)(t - 1) * BB * Kp : h0f;
        const float*  cin  = t ? cbuf + (size_t)((t - 1) & 1) * BB * HH : c0;
        float*  cout = cbuf + (size_t)(t & 1) * BB * HH;
        __half* yout = xout + (size_t)t * BB * Kp;
        const float* xp = xproj + (size_t)t * BB * N4p;

        // Prefetch xp for this step (independent of MMA; hides DRAM latency)
        float4 xv[NPF];
        #pragma unroll
        for (int s = 0; s < NPF; s++) {
            int p  = tid + s * 256;
            int b  = p >> B_SH;
            int jl = p & JL_M;
            xv[s] = *reinterpret_cast<const float4*>(
                xp + (size_t)(b0 + b) * N4p + n0 + jl * 4);
        }

        float acc[IM][2][4] = {};

#define ISSUE_H(grp, stage) do {                                           \
        cp16(sH + (unsigned)(stage) * 5120u + (crow * 40 + cko) * 2,       \
             hsrc + (size_t)(b0 + crow) * Kp + ((grp) << 5) + cko);        \
        cp_commit();                                                       \
    } while (0)

        ISSUE_H(0, 0); ISSUE_H(1, 1); ISSUE_H(2, 2);
        ISSUE_H(3, 3); ISSUE_H(4, 4);

        for (int it = 0; it < nk; it++) {
            if (it + 5 <= nk) asm volatile("cp.async.wait_group 4;");
            else              asm volatile("cp.async.wait_group 0;");
            __syncthreads();
            if (it + 5 < nk) { int st = (it + 5) % 6; ISSUE_H(it + 5, st); }

            unsigned ab = sH + (unsigned)(it % 6) * 5120u;
            int k0 = it << 5;
            #pragma unroll
            for (int kk = 0; kk < 32; kk += 16) {
                unsigned af[IM][4], bf[2][2];
                #pragma unroll
                for (int i = 0; i < IM; i++) {
                    int ar = wm * MW + i * 16;
                    ldsm_x4(af[i][0], af[i][1], af[i][2], af[i][3],
                            ab + (unsigned)(((ar + a_row) * 40 + kk + a_col) * 2));
                }
                {
                    int br = wn * 16;
                    ldsm_x4(bf[0][0], bf[0][1], bf[1][0], bf[1][1],
                            sW + (unsigned)(((br + b_row) * pitch + k0 + kk + b_col) * 2));
                }
                #pragma unroll
                for (int i = 0; i < IM; i++)
                    #pragma unroll
                    for (int j = 0; j < 2; j++)
                        mma_f16(acc[i][j], af[i][0], af[i][1], af[i][2], af[i][3],
                                bf[j][0], bf[j][1]);
            }
        }
#undef ISSUE_H

        int g  = lane >> 2, tg = lane & 3;
        #pragma unroll
        for (int i = 0; i < IM; i++) {
            int r0 = wm * MW + i * 16 + g;
            #pragma unroll
            for (int j = 0; j < 2; j++) {
                int col = wn * 16 + j * 8 + 2 * tg;
                gates[r0 * (NTILE + 1) + col]           = acc[i][j][0];
                gates[r0 * (NTILE + 1) + col + 1]       = acc[i][j][1];
                gates[(r0 + 8) * (NTILE + 1) + col]     = acc[i][j][2];
                gates[(r0 + 8) * (NTILE + 1) + col + 1] = acc[i][j][3];
            }
        }
        __syncthreads();

        #pragma unroll
        for (int s = 0; s < NPF; s++) {
            int p  = tid + s * 256;
            int b  = p >> B_SH;
            int jl = p & JL_M;
            int j  = jbase + jl;
            if (j < nh) {
                int bg = b0 + b;
                float gi = gates[b * (NTILE + 1) + jl * 4 + 0] + xv[s].x;
                float gf = gates[b * (NTILE + 1) + jl * 4 + 1] + xv[s].y;
                float gg = gates[b * (NTILE + 1) + jl * 4 + 2] + xv[s].z;
                float go = gates[b * (NTILE + 1) + jl * 4 + 3] + xv[s].w;
                float iv = fsigmoid(gi);
                float fv = fsigmoid(gf);
                float gv = ftanh(gg);
                float ov = fsigmoid(go);
                float cv = fv * cin[(size_t)bg * nh + j] + iv * gv;
                float hv = ov * ftanh(cv);
                cout[(size_t)bg * nh + j] = cv;
                yout[(size_t)bg * Kp + j] = __float2half(hv);
            }
        }

        if (t + 1 < TT) grid_bar(nblocks);
    }
}

// ---------------------------------------------------------------------------
// Layer driver
// ---------------------------------------------------------------------------
static void run_layer(const __half* x_in, int Kp_in, int K_in, int nh, int Kp_h,
                      int N4p, bool small_layer,
                      const float* W_ih, const float* W_hh,
                      const float* b_ih, const float* b_hh,
                      const float* h0, const float* c0,
                      __half* x_out,
                      __half* Wih, __half* Whh, float* bias,
                      float* xproj, float* cbuf, __half* h0f)
{
    reorder_f16<<<N4p, 256>>>(W_ih, Wih, nh, K_in, Kp_in);
    reorder_f16<<<N4p, 256>>>(W_hh, Whh, nh, nh, Kp_h);
    combine_bias<<<(N4p + 255) / 256, 256>>>(b_ih, b_hh, bias, nh, N4p);
    conv_h0<<<BB, 256>>>(h0, h0f, nh, Kp_h);

    // Input projection: xproj = x_in @ Wih^T + bias
    {
        dim3 grid(N4p / 128, (TT * BB) / 128);
        gemm_f16<<<grid, 256, 61440>>>(x_in, Wih, bias, xproj, N4p, Kp_in,
                                       Kp_in, Kp_in, N4p);
    }

    // Persistent recurrence: single launch for all 70 steps
    int pitch = Kp_h + 8;
    if (!small_layer) {
        size_t smem = (size_t)64 * pitch * 2 + 6 * 2560 * 2 + 64 * 65 * 4;
        dim3 grid(N4p / 64, 2);
        unsigned nblocks = (N4p / 64) * 2;
        lstm_persist<64><<<grid, 256, smem>>>(h0f, c0, Whh, xproj, cbuf, x_out,
                                              nh, Kp_h, N4p, pitch, nblocks);
    } else {
        size_t smem = (size_t)32 * pitch * 2 + 6 * 2560 * 2 + 64 * 33 * 4;
        dim3 grid(N4p / 32, 2);
        unsigned nblocks = (N4p / 32) * 2;
        lstm_persist<32><<<grid, 256, smem>>>(h0f, c0, Whh, xproj, cbuf, x_out,
                                              nh, Kp_h, N4p, pitch, nblocks);
    }
}

extern "C" void kernel_launch(void* const* d_in, const int* in_sizes, int n_in,
                              void* d_out, int out_size)
{
    const int*   tokens = (const int*)  d_in[0];
    const float* h0_0   = (const float*)d_in[1];
    const float* c0_0   = (const float*)d_in[2];
    const float* h0_1   = (const float*)d_in[3];
    const float* c0_1   = (const float*)d_in[4];
    const float* h0_2   = (const float*)d_in[5];
    const float* c0_2   = (const float*)d_in[6];
    const float* embw   = (const float*)d_in[7];
    const float* W_ih0  = (const float*)d_in[8];
    const float* W_hh0  = (const float*)d_in[9];
    const float* b_ih0  = (const float*)d_in[10];
    const float* b_hh0  = (const float*)d_in[11];
    const float* W_ih1  = (const float*)d_in[12];
    const float* W_hh1  = (const float*)d_in[13];
    const float* b_ih1  = (const float*)d_in[14];
    const float* b_hh1  = (const float*)d_in[15];
    const float* W_ih2  = (const float*)d_in[16];
    const float* W_hh2  = (const float*)d_in[17];
    const float* b_ih2  = (const float*)d_in[18];
    const float* b_hh2  = (const float*)d_in[19];
    const float* dec_b  = (const float*)d_in[20];
    float* logits = (float*)d_out;

    __half *x0, *x1, *x2, *x3, *embf, *Wih, *Whh, *h0f;
    float *bias, *xproj, *cbuf;
    cudaGetSymbolAddress((void**)&x0,    g_x0);
    cudaGetSymbolAddress((void**)&x1,    g_x1);
    cudaGetSymbolAddress((void**)&x2,    g_x2);
    cudaGetSymbolAddress((void**)&x3,    g_x3);
    cudaGetSymbolAddress((void**)&embf,  g_embf);
    cudaGetSymbolAddress((void**)&Wih,   g_Wih);
    cudaGetSymbolAddress((void**)&Whh,   g_Whh);
    cudaGetSymbolAddress((void**)&bias,  g_bias);
    cudaGetSymbolAddress((void**)&xproj, g_xproj);
    cudaGetSymbolAddress((void**)&cbuf,  g_c);
    cudaGetSymbolAddress((void**)&h0f,   g_h0f);

    cudaFuncSetAttribute(gemm_f16, cudaFuncAttributeMaxDynamicSharedMemorySize,
                         61440);
    cudaFuncSetAttribute(lstm_persist<64>,
                         cudaFuncAttributeMaxDynamicSharedMemorySize,
                         64 * (KP_H + 8) * 2 + 6 * 2560 * 2 + 64 * 65 * 4);
    cudaFuncSetAttribute(lstm_persist<32>,
                         cudaFuncAttributeMaxDynamicSharedMemorySize,
                         32 * (KP_E + 8) * 2 + 6 * 2560 * 2 + 64 * 33 * 4);

    // Preprocess: embedding gather + fp16 embedding table
    embed_f16<<<TT * BB, 256>>>(tokens, embw, x0);
    conv_emb<<<VV, 128>>>(embw, embf);

    // Three LSTM layers
    run_layer(x0, KP_E, EE, HH, KP_H, N4P_H, false, W_ih0, W_hh0, b_ih0, b_hh0,
              h0_0, c0_0, x1, Wih, Whh, bias, xproj, cbuf, h0f);
    run_layer(x1, KP_H, HH, HH, KP_H, N4P_H, false, W_ih1, W_hh1, b_ih1, b_hh1,
              h0_1, c0_1, x2, Wih, Whh, bias, xproj, cbuf, h0f);
    run_layer(x2, KP_H, HH, EE, KP_E, N4P_E, true, W_ih2, W_hh2, b_ih2, b_hh2,
              h0_2, c0_2, x3, Wih, Whh, bias, xproj, cbuf, h0f);

    // Tied decoder: logits = x3 @ embf^T + dec_b
    {
        dim3 grid((VV + 127) / 128, (TT * BB) / 128);
        gemm_f16<<<grid, 256, 61440>>>(x3, embf, dec_b, logits, VV, KP_E,
                                       KP_E, KP_E, VV);
    }
}

// round 12
// speedup vs baseline: 1.2442x; 1.0512x over previous
#include <cuda_runtime.h>
#include <cuda_fp16.h>
#include <math.h>
#include <stdint.h>

// Problem constants
#define TT 70
#define BB 128
#define EE 400
#define HH 1150
#define VV 33278

// Padded dims (K multiples of 32, strides 16B-aligned)
#define KP_E 416
#define KP_H 1152
#define N4P_H 4608
#define N4P_E 1664

// ---------------------------------------------------------------------------
// Scratch (device globals; zero-initialized at module load — pad columns of
// activation buffers are NEVER written non-zero, so no runtime zeroing needed)
// ---------------------------------------------------------------------------
__device__ __half g_x0  [TT * BB * KP_E];
__device__ __half g_x1  [TT * BB * KP_H];
__device__ __half g_x2  [TT * BB * KP_H];
__device__ __half g_x3  [TT * BB * KP_E];
__device__ __half g_embf[VV * KP_E];
__device__ __half g_Wih [N4P_H * KP_H];
__device__ __half g_Whh [N4P_H * KP_H];
__device__ float  g_bias[N4P_H];
__device__ float  g_xproj[TT * BB * N4P_H];
__device__ float  g_c   [2 * BB * HH];
__device__ __half g_h0f [BB * KP_H];
__device__ unsigned g_count;            // grid barrier arrival counter
__device__ volatile unsigned g_gen;     // grid barrier generation

// ---------------------------------------------------------------------------
// PTX helpers
// ---------------------------------------------------------------------------
__device__ __forceinline__ void cp16(unsigned s, const void* g) {
    asm volatile("cp.async.cg.shared.global [%0], [%1], 16;" :: "r"(s), "l"(g));
}
__device__ __forceinline__ void cp16z(unsigned s, const void* g, int sz) {
    asm volatile("cp.async.cg.shared.global [%0], [%1], 16, %2;" :: "r"(s), "l"(g), "r"(sz));
}
__device__ __forceinline__ void cp_commit() {
    asm volatile("cp.async.commit_group;");
}
__device__ __forceinline__ void mma_f16(float c[4], unsigned a0, unsigned a1,
                                        unsigned a2, unsigned a3,
                                        unsigned b0, unsigned b1)
{
    asm("mma.sync.aligned.m16n8k16.row.col.f32.f16.f16.f32 "
        "{%0,%1,%2,%3},{%4,%5,%6,%7},{%8,%9},{%0,%1,%2,%3};"
        : "+f"(c[0]), "+f"(c[1]), "+f"(c[2]), "+f"(c[3])
        : "r"(a0), "r"(a1), "r"(a2), "r"(a3), "r"(b0), "r"(b1));
}
__device__ __forceinline__ void ldsm_x4(unsigned& r0, unsigned& r1,
                                        unsigned& r2, unsigned& r3, uint32_t a)
{
    asm volatile("ldmatrix.sync.aligned.m8n8.x4.shared.b16 {%0,%1,%2,%3}, [%4];"
                 : "=r"(r0), "=r"(r1), "=r"(r2), "=r"(r3) : "r"(a));
}
__device__ __forceinline__ float fsigmoid(float x) {
    return 1.0f / (1.0f + __expf(-x));
}
__device__ __forceinline__ float ftanh(float x) {
    return 2.0f / (1.0f + __expf(-2.0f * x)) - 1.0f;
}

// Grid-wide barrier (all blocks co-resident by construction)
__device__ __forceinline__ void grid_bar(unsigned nblocks) {
    __syncthreads();
    if (threadIdx.x == 0) {
        unsigned old = g_gen;
        __threadfence();
        unsigned t = atomicAdd(&g_count, 1u);
        if (t == nblocks - 1u) {
            g_count = 0u;
            __threadfence();
            g_gen = old + 1u;
        } else {
            while (g_gen == old) { }
        }
        __threadfence();
    }
    __syncthreads();
}

// ---------------------------------------------------------------------------
// Preprocessing kernels (vectorized: float2 loads -> half2 stores; all K even)
// ---------------------------------------------------------------------------
__global__ void embed_f16(const int* __restrict__ tokens,
                          const float* __restrict__ emb,
                          __half* __restrict__ out)
{
    int tb = blockIdx.x;
    int tok = tokens[tb];
    const float2* src = (const float2*)(emb + (size_t)tok * EE);
    __half2* dst = (__half2*)(out + (size_t)tb * KP_E);
    for (int e = threadIdx.x; e < KP_E / 2; e += blockDim.x) {
        float2 v = (2 * e < EE) ? src[e] : make_float2(0.f, 0.f);
        dst[e] = __floats2half2_rn(v.x, v.y);
    }
}

__global__ void conv_emb(const float* __restrict__ emb, __half* __restrict__ out)
{
    int row = blockIdx.x;
    const float2* src = (const float2*)(emb + (size_t)row * EE);
    __half2* dst = (__half2*)(out + (size_t)row * KP_E);
    for (int e = threadIdx.x; e < KP_E / 2; e += blockDim.x) {
        float2 v = (2 * e < EE) ? src[e] : make_float2(0.f, 0.f);
        dst[e] = __floats2half2_rn(v.x, v.y);
    }
}

__global__ void reorder_f16(const float* __restrict__ W, __half* __restrict__ Wr,
                            int nh, int K, int Kp)
{
    int row = blockIdx.x;
    int j = row >> 2, g = row & 3;
    bool valid = (row < 4 * nh);
    const float2* src = (const float2*)(W + (size_t)(g * nh + j) * K);
    __half2* dst = (__half2*)(Wr + (size_t)row * Kp);
    for (int k = threadIdx.x; k < Kp / 2; k += blockDim.x) {
        float2 v = (valid && 2 * k < K) ? src[k] : make_float2(0.f, 0.f);
        dst[k] = __floats2half2_rn(v.x, v.y);
    }
}

__global__ void combine_bias(const float* __restrict__ b1, const float* __restrict__ b2,
                             float* __restrict__ br, int nh, int N4p)
{
    int r = blockIdx.x * blockDim.x + threadIdx.x;
    if (r < N4p) {
        int j = r >> 2, g = r & 3;
        br[r] = (r < 4 * nh) ? b1[g * nh + j] + b2[g * nh + j] : 0.0f;
    }
}

__global__ void conv_h0(const float* __restrict__ h0, __half* __restrict__ out,
                        int nh, int Kp)
{
    int b = blockIdx.x;
    const float2* src = (const float2*)(h0 + (size_t)b * nh);
    __half2* dst = (__half2*)(out + (size_t)b * Kp);
    for (int k = threadIdx.x; k < Kp / 2; k += blockDim.x) {
        float2 v = (2 * k < nh) ? src[k] : make_float2(0.f, 0.f);
        dst[k] = __floats2half2_rn(v.x, v.y);
    }
}

// ---------------------------------------------------------------------------
// FP16 GEMM (NT), 3-stage cp.async pipeline + ldmatrix operand fetch.
// C[m,n] = sum_k A[m,k]*B[n,k] + bias[n]
// Block 128x128, BK=32, 256 threads (8 warps 2m x 4n), warp tile 64x32.
// launch_bounds(256, 2): cap regs at 128 -> 2 CTAs/SM (occupancy probe).
// ---------------------------------------------------------------------------
__global__ void __launch_bounds__(256, 2) gemm_f16(
    const __half* __restrict__ A, const __half* __restrict__ B,
    const float* __restrict__ bias, float* __restrict__ C,
    int N, int Kp, int lda, int ldb, int ldc)
{
    extern __shared__ __align__(16) char dsm[];
    __half* Asm = (__half*)dsm;              // 3 stages x 5120 halfs
    __half* Bsm = Asm + 3 * 5120;            // 3 stages x 5120 halfs

    int tid  = threadIdx.x;
    int warp = tid >> 5, lane = tid & 31;
    int wm = warp & 1, wn = warp >> 1;
    int g  = lane >> 2, tg = lane & 3;
    int m0 = blockIdx.y * 128;
    int n0 = blockIdx.x * 128;

    unsigned sA = (unsigned)__cvta_generic_to_shared(Asm);
    unsigned sB = (unsigned)__cvta_generic_to_shared(Bsm);

    // ldmatrix lane offsets
    int a_row = (lane & 7) + ((lane >> 3) & 1) * 8;
    int a_col = (lane >> 4) * 8;
    int b_row = (lane & 7) + (lane >> 4) * 8;
    int b_col = ((lane >> 3) & 1) * 8;

    int crow[2], cko[2];
    #pragma unroll
    for (int s = 0; s < 2; s++) {
        int c = tid + s * 256;
        crow[s] = c >> 2;
        cko[s]  = (c & 3) * 8;
    }

    float acc[4][4][4] = {};
    int nk = Kp >> 5;     // >= 13 always

#define ISSUE_AB(grp, stage) do {                                              \
        int _kt = (grp) << 5;                                                  \
        unsigned _so = (unsigned)(stage) * 10240u;                             \
        _Pragma("unroll")                                                      \
        for (int s = 0; s < 2; s++) {                                          \
            int row = crow[s], ko = cko[s];                                    \
            cp16(sA + _so + (row * 40 + ko) * 2,                               \
                 A + (size_t)(m0 + row) * lda + _kt + ko);                     \
            int gn = n0 + row;                                                 \
            int sz = (gn < N) ? 16 : 0;                                        \
            const __half* gb = B + (size_t)(gn < N ? gn : 0) * ldb + _kt + ko; \
            cp16z(sB + _so + (row * 40 + ko) * 2, gb, sz);                     \
        }                                                                      \
        cp_commit();                                                           \
    } while (0)

    ISSUE_AB(0, 0);
    ISSUE_AB(1, 1);

    for (int it = 0; it < nk; it++) {
        if (it + 2 <= nk) asm volatile("cp.async.wait_group 1;");
        else              asm volatile("cp.async.wait_group 0;");
        __syncthreads();
        if (it + 2 < nk) { int st = (it + 2) % 3; ISSUE_AB(it + 2, st); }

        unsigned ab = sA + (unsigned)(it % 3) * 10240u;
        unsigned bb = sB + (unsigned)(it % 3) * 10240u;
        #pragma unroll
        for (int kk = 0; kk < 32; kk += 16) {
            unsigned af[4][4], bf[4][2];
            #pragma unroll
            for (int i = 0; i < 4; i++) {
                int ar = wm * 64 + i * 16;
                ldsm_x4(af[i][0], af[i][1], af[i][2], af[i][3],
                        ab + (unsigned)(((ar + a_row) * 40 + kk + a_col) * 2));
            }
            #pragma unroll
            for (int j = 0; j < 4; j += 2) {
                int br = wn * 32 + j * 8;
                ldsm_x4(bf[j][0], bf[j][1], bf[j + 1][0], bf[j + 1][1],
                        bb + (unsigned)(((br + b_row) * 40 + kk + b_col) * 2));
            }
            #pragma unroll
            for (int i = 0; i < 4; i++)
                #pragma unroll
                for (int j = 0; j < 4; j++)
                    mma_f16(acc[i][j], af[i][0], af[i][1], af[i][2], af[i][3],
                            bf[j][0], bf[j][1]);
        }
    }
#undef ISSUE_AB

    #pragma unroll
    for (int i = 0; i < 4; i++) {
        int r0 = m0 + wm * 64 + i * 16 + g;
        #pragma unroll
        for (int j = 0; j < 4; j++) {
            int col = n0 + wn * 32 + j * 8 + 2 * tg;
            if (col < N) {
                float bz  = bias ? bias[col] : 0.0f;
                float bz1 = bias ? bias[col + 1] : 0.0f;
                float2 v0 = {acc[i][j][0] + bz, acc[i][j][1] + bz1};
                float2 v1 = {acc[i][j][2] + bz, acc[i][j][3] + bz1};
                *reinterpret_cast<float2*>(C + (size_t)r0 * ldc + col) = v0;
                *reinterpret_cast<float2*>(C + (size_t)(r0 + 8) * ldc + col) = v1;
            }
        }
    }
}

// ---------------------------------------------------------------------------
// Persistent LSTM recurrence, templated on gate-column tile NTILE (64 or 32).
// NTILE=64: 8 warps as 2m x 4n (warp 32x16). NTILE=32: 4m x 2n (warp 16x16).
// W slice resident in smem; h streamed per step (6-stage cp.async);
// xp prefetched into registers at step start; grid barrier between steps.
// ---------------------------------------------------------------------------
template<int NTILE>
__global__ void __launch_bounds__(256) lstm_persist(
    const __half* __restrict__ h0f,
    const float*  __restrict__ c0,
    const __half* __restrict__ Wg,
    const float*  __restrict__ xproj,
    float* __restrict__ cbuf,
    __half* __restrict__ xout,
    int nh, int Kp, int N4p, int pitch, unsigned nblocks)
{
    constexpr int IM   = (NTILE == 64) ? 2 : 1;       // m-frags per warp
    constexpr int MW   = 16 * IM;                     // rows per m-warp
    constexpr int NPF  = NTILE / 16;                  // pointwise iters (4 or 2)
    constexpr int JL_M = NTILE / 4 - 1;               // jl mask
    constexpr int B_SH = (NTILE == 64) ? 4 : 3;       // b shift

    extern __shared__ __align__(16) char dsm[];
    __half* Ws   = (__half*)dsm;                      // NTILE x pitch
    __half* Hs   = Ws + NTILE * pitch;                // 6 stages x 2560
    float*  gates = (float*)(Hs + 6 * 2560);          // 64 x (NTILE+1)

    int tid  = threadIdx.x;
    int warp = tid >> 5, lane = tid & 31;
    int wm = (NTILE == 64) ? (warp & 1) : (warp >> 1);
    int wn = (NTILE == 64) ? (warp >> 1) : (warp & 1);
    int n0 = blockIdx.x * NTILE;
    int b0 = blockIdx.y * 64;

    unsigned sW = (unsigned)__cvta_generic_to_shared(Ws);
    unsigned sH = (unsigned)__cvta_generic_to_shared(Hs);

    // ldmatrix lane offsets
    int a_row = (lane & 7) + ((lane >> 3) & 1) * 8;
    int a_col = (lane >> 4) * 8;
    int b_row = (lane & 7) + (lane >> 4) * 8;
    int b_col = ((lane >> 3) & 1) * 8;

    int kch = Kp >> 3;
    for (int c = tid; c < NTILE * kch; c += 256) {
        int row = c / kch;
        int kc  = (c - row * kch) << 3;
        cp16(sW + (unsigned)(row * pitch + kc) * 2, Wg + (size_t)(n0 + row) * Kp + kc);
    }
    cp_commit();
    asm volatile("cp.async.wait_group 0;");
    __syncthreads();

    int nk   = Kp >> 5;
    int crow = tid >> 2;
    int cko  = (tid & 3) * 8;
    int jbase = n0 >> 2;

    for (int t = 0; t < TT; t++) {
        const __half* hsrc = t ? xout + (size_t)(t - 1) * BB * Kp : h0f;
        const float*  cin  = t ? cbuf + (size_t)((t - 1) & 1) * BB * HH : c0;
        float*  cout = cbuf + (size_t)(t & 1) * BB * HH;
        __half* yout = xout + (size_t)t * BB * Kp;
        const float* xp = xproj + (size_t)t * BB * N4p;

        // Prefetch xp for this step (independent of MMA; hides DRAM latency)
        float4 xv[NPF];
        #pragma unroll
        for (int s = 0; s < NPF; s++) {
            int p  = tid + s * 256;
            int b  = p >> B_SH;
            int jl = p & JL_M;
            xv[s] = *reinterpret_cast<const float4*>(
                xp + (size_t)(b0 + b) * N4p + n0 + jl * 4);
        }

        float acc[IM][2][4] = {};

#define ISSUE_H(grp, stage) do {                                           \
        cp16(sH + (unsigned)(stage) * 5120u + (crow * 40 + cko) * 2,       \
             hsrc + (size_t)(b0 + crow) * Kp + ((grp) << 5) + cko);        \
        cp_commit();                                                       \
    } while (0)

        ISSUE_H(0, 0); ISSUE_H(1, 1); ISSUE_H(2, 2);
        ISSUE_H(3, 3); ISSUE_H(4, 4);

        for (int it = 0; it < nk; it++) {
            if (it + 5 <= nk) asm volatile("cp.async.wait_group 4;");
            else              asm volatile("cp.async.wait_group 0;");
            __syncthreads();
            if (it + 5 < nk) { int st = (it + 5) % 6; ISSUE_H(it + 5, st); }

            unsigned ab = sH + (unsigned)(it % 6) * 5120u;
            int k0 = it << 5;
            #pragma unroll
            for (int kk = 0; kk < 32; kk += 16) {
                unsigned af[IM][4], bf[2][2];
                #pragma unroll
                for (int i = 0; i < IM; i++) {
                    int ar = wm * MW + i * 16;
                    ldsm_x4(af[i][0], af[i][1], af[i][2], af[i][3],
                            ab + (unsigned)(((ar + a_row) * 40 + kk + a_col) * 2));
                }
                {
                    int br = wn * 16;
                    ldsm_x4(bf[0][0], bf[0][1], bf[1][0], bf[1][1],
                            sW + (unsigned)(((br + b_row) * pitch + k0 + kk + b_col) * 2));
                }
                #pragma unroll
                for (int i = 0; i < IM; i++)
                    #pragma unroll
                    for (int j = 0; j < 2; j++)
                        mma_f16(acc[i][j], af[i][0], af[i][1], af[i][2], af[i][3],
                                bf[j][0], bf[j][1]);
            }
        }
#undef ISSUE_H

        int g  = lane >> 2, tg = lane & 3;
        #pragma unroll
        for (int i = 0; i < IM; i++) {
            int r0 = wm * MW + i * 16 + g;
            #pragma unroll
            for (int j = 0; j < 2; j++) {
                int col = wn * 16 + j * 8 + 2 * tg;
                gates[r0 * (NTILE + 1) + col]           = acc[i][j][0];
                gates[r0 * (NTILE + 1) + col + 1]       = acc[i][j][1];
                gates[(r0 + 8) * (NTILE + 1) + col]     = acc[i][j][2];
                gates[(r0 + 8) * (NTILE + 1) + col + 1] = acc[i][j][3];
            }
        }
        __syncthreads();

        #pragma unroll
        for (int s = 0; s < NPF; s++) {
            int p  = tid + s * 256;
            int b  = p >> B_SH;
            int jl = p & JL_M;
            int j  = jbase + jl;
            if (j < nh) {
                int bg = b0 + b;
                float gi = gates[b * (NTILE + 1) + jl * 4 + 0] + xv[s].x;
                float gf = gates[b * (NTILE + 1) + jl * 4 + 1] + xv[s].y;
                float gg = gates[b * (NTILE + 1) + jl * 4 + 2] + xv[s].z;
                float go = gates[b * (NTILE + 1) + jl * 4 + 3] + xv[s].w;
                float iv = fsigmoid(gi);
                float fv = fsigmoid(gf);
                float gv = ftanh(gg);
                float ov = fsigmoid(go);
                float cv = fv * cin[(size_t)bg * nh + j] + iv * gv;
                float hv = ov * ftanh(cv);
                cout[(size_t)bg * nh + j] = cv;
                yout[(size_t)bg * Kp + j] = __float2half(hv);
            }
        }

        if (t + 1 < TT) grid_bar(nblocks);
    }
}

// ---------------------------------------------------------------------------
// Layer driver
// ---------------------------------------------------------------------------
static void run_layer(const __half* x_in, int Kp_in, int K_in, int nh, int Kp_h,
                      int N4p, bool small_layer,
                      const float* W_ih, const float* W_hh,
                      const float* b_ih, const float* b_hh,
                      const float* h0, const float* c0,
                      __half* x_out,
                      __half* Wih, __half* Whh, float* bias,
                      float* xproj, float* cbuf, __half* h0f)
{
    reorder_f16<<<N4p, 256>>>(W_ih, Wih, nh, K_in, Kp_in);
    reorder_f16<<<N4p, 256>>>(W_hh, Whh, nh, nh, Kp_h);
    combine_bias<<<(N4p + 255) / 256, 256>>>(b_ih, b_hh, bias, nh, N4p);
    conv_h0<<<BB, 256>>>(h0, h0f, nh, Kp_h);

    // Input projection: xproj = x_in @ Wih^T + bias
    {
        dim3 grid(N4p / 128, (TT * BB) / 128);
        gemm_f16<<<grid, 256, 61440>>>(x_in, Wih, bias, xproj, N4p, Kp_in,
                                       Kp_in, Kp_in, N4p);
    }

    // Persistent recurrence: single launch for all 70 steps
    int pitch = Kp_h + 8;
    if (!small_layer) {
        size_t smem = (size_t)64 * pitch * 2 + 6 * 2560 * 2 + 64 * 65 * 4;
        dim3 grid(N4p / 64, 2);
        unsigned nblocks = (N4p / 64) * 2;
        lstm_persist<64><<<grid, 256, smem>>>(h0f, c0, Whh, xproj, cbuf, x_out,
                                              nh, Kp_h, N4p, pitch, nblocks);
    } else {
        size_t smem = (size_t)32 * pitch * 2 + 6 * 2560 * 2 + 64 * 33 * 4;
        dim3 grid(N4p / 32, 2);
        unsigned nblocks = (N4p / 32) * 2;
        lstm_persist<32><<<grid, 256, smem>>>(h0f, c0, Whh, xproj, cbuf, x_out,
                                              nh, Kp_h, N4p, pitch, nblocks);
    }
}

extern "C" void kernel_launch(void* const* d_in, const int* in_sizes, int n_in,
                              void* d_out, int out_size)
{
    const int*   tokens = (const int*)  d_in[0];
    const float* h0_0   = (const float*)d_in[1];
    const float* c0_0   = (const float*)d_in[2];
    const float* h0_1   = (const float*)d_in[3];
    const float* c0_1   = (const float*)d_in[4];
    const float* h0_2   = (const float*)d_in[5];
    const float* c0_2   = (const float*)d_in[6];
    const float* embw   = (const float*)d_in[7];
    const float* W_ih0  = (const float*)d_in[8];
    const float* W_hh0  = (const float*)d_in[9];
    const float* b_ih0  = (const float*)d_in[10];
    const float* b_hh0  = (const float*)d_in[11];
    const float* W_ih1  = (const float*)d_in[12];
    const float* W_hh1  = (const float*)d_in[13];
    const float* b_ih1  = (const float*)d_in[14];
    const float* b_hh1  = (const float*)d_in[15];
    const float* W_ih2  = (const float*)d_in[16];
    const float* W_hh2  = (const float*)d_in[17];
    const float* b_ih2  = (const float*)d_in[18];
    const float* b_hh2  = (const float*)d_in[19];
    const float* dec_b  = (const float*)d_in[20];
    float* logits = (float*)d_out;

    __half *x0, *x1, *x2, *x3, *embf, *Wih, *Whh, *h0f;
    float *bias, *xproj, *cbuf;
    cudaGetSymbolAddress((void**)&x0,    g_x0);
    cudaGetSymbolAddress((void**)&x1,    g_x1);
    cudaGetSymbolAddress((void**)&x2,    g_x2);
    cudaGetSymbolAddress((void**)&x3,    g_x3);
    cudaGetSymbolAddress((void**)&embf,  g_embf);
    cudaGetSymbolAddress((void**)&Wih,   g_Wih);
    cudaGetSymbolAddress((void**)&Whh,   g_Whh);
    cudaGetSymbolAddress((void**)&bias,  g_bias);
    cudaGetSymbolAddress((void**)&xproj, g_xproj);
    cudaGetSymbolAddress((void**)&cbuf,  g_c);
    cudaGetSymbolAddress((void**)&h0f,   g_h0f);

    cudaFuncSetAttribute(gemm_f16, cudaFuncAttributeMaxDynamicSharedMemorySize,
                         61440);
    cudaFuncSetAttribute(lstm_persist<64>,
                         cudaFuncAttributeMaxDynamicSharedMemorySize,
                         64 * (KP_H + 8) * 2 + 6 * 2560 * 2 + 64 * 65 * 4);
    cudaFuncSetAttribute(lstm_persist<32>,
                         cudaFuncAttributeMaxDynamicSharedMemorySize,
                         32 * (KP_E + 8) * 2 + 6 * 2560 * 2 + 64 * 33 * 4);

    // Preprocess: embedding gather + fp16 embedding table
    embed_f16<<<TT * BB, 256>>>(tokens, embw, x0);
    conv_emb<<<VV, 128>>>(embw, embf);

    // Three LSTM layers
    run_layer(x0, KP_E, EE, HH, KP_H, N4P_H, false, W_ih0, W_hh0, b_ih0, b_hh0,
              h0_0, c0_0, x1, Wih, Whh, bias, xproj, cbuf, h0f);
    run_layer(x1, KP_H, HH, HH, KP_H, N4P_H, false, W_ih1, W_hh1, b_ih1, b_hh1,
              h0_1, c0_1, x2, Wih, Whh, bias, xproj, cbuf, h0f);
    run_layer(x2, KP_H, HH, EE, KP_E, N4P_E, true, W_ih2, W_hh2, b_ih2, b_hh2,
              h0_2, c0_2, x3, Wih, Whh, bias, xproj, cbuf, h0f);

    // Tied decoder: logits = x3 @ embf^T + dec_b
    {
        dim3 grid((VV + 127) / 128, (TT * BB) / 128);
        gemm_f16<<<grid, 256, 61440>>>(x3, embf, dec_b, logits, VV, KP_E,
                                       KP_E, KP_E, VV);
    }
}

// round 13
// speedup vs baseline: 1.2772x; 1.0265x over previous
#include <cuda_runtime.h>
#include <cuda_fp16.h>
#include <math.h>
#include <stdint.h>

// Problem constants
#define TT 70
#define BB 128
#define EE 400
#define HH 1150
#define VV 33278

// Padded dims (K multiples of 32, strides 16B-aligned)
#define KP_E 416
#define KP_H 1152
#define N4P_H 4608
#define N4P_E 1664

// ---------------------------------------------------------------------------
// Scratch (device globals; zero-initialized at module load — pad columns of
// activation buffers are NEVER written non-zero, so no runtime zeroing needed)
// ---------------------------------------------------------------------------
__device__ __half g_x0  [TT * BB * KP_E];
__device__ __half g_x1  [TT * BB * KP_H];
__device__ __half g_x2  [TT * BB * KP_H];
__device__ __half g_x3  [TT * BB * KP_E];
__device__ __half g_embf[VV * KP_E];
__device__ __half g_Wih [N4P_H * KP_H];
__device__ __half g_Whh [N4P_H * KP_H];
__device__ float  g_bias[N4P_H];
__device__ float  g_xproj[TT * BB * N4P_H];
__device__ float  g_c   [2 * BB * HH];
__device__ __half g_h0f [BB * KP_H];
__device__ unsigned g_count;            // grid barrier arrival counter
__device__ volatile unsigned g_gen;     // grid barrier generation

// ---------------------------------------------------------------------------
// PTX helpers
// ---------------------------------------------------------------------------
__device__ __forceinline__ void cp16(unsigned s, const void* g) {
    asm volatile("cp.async.cg.shared.global [%0], [%1], 16;" :: "r"(s), "l"(g));
}
__device__ __forceinline__ void cp16z(unsigned s, const void* g, int sz) {
    asm volatile("cp.async.cg.shared.global [%0], [%1], 16, %2;" :: "r"(s), "l"(g), "r"(sz));
}
__device__ __forceinline__ void cp_commit() {
    asm volatile("cp.async.commit_group;");
}
__device__ __forceinline__ void mma_f16(float c[4], unsigned a0, unsigned a1,
                                        unsigned a2, unsigned a3,
                                        unsigned b0, unsigned b1)
{
    asm("mma.sync.aligned.m16n8k16.row.col.f32.f16.f16.f32 "
        "{%0,%1,%2,%3},{%4,%5,%6,%7},{%8,%9},{%0,%1,%2,%3};"
        : "+f"(c[0]), "+f"(c[1]), "+f"(c[2]), "+f"(c[3])
        : "r"(a0), "r"(a1), "r"(a2), "r"(a3), "r"(b0), "r"(b1));
}
__device__ __forceinline__ void ldsm_x4(unsigned& r0, unsigned& r1,
                                        unsigned& r2, unsigned& r3, uint32_t a)
{
    asm volatile("ldmatrix.sync.aligned.m8n8.x4.shared.b16 {%0,%1,%2,%3}, [%4];"
                 : "=r"(r0), "=r"(r1), "=r"(r2), "=r"(r3) : "r"(a));
}
__device__ __forceinline__ float fsigmoid(float x) {
    return 1.0f / (1.0f + __expf(-x));
}
__device__ __forceinline__ float ftanh(float x) {
    return 2.0f / (1.0f + __expf(-2.0f * x)) - 1.0f;
}

// Grid-wide barrier (all blocks co-resident by construction)
__device__ __forceinline__ void grid_bar(unsigned nblocks) {
    __syncthreads();
    if (threadIdx.x == 0) {
        unsigned old = g_gen;
        __threadfence();
        unsigned t = atomicAdd(&g_count, 1u);
        if (t == nblocks - 1u) {
            g_count = 0u;
            __threadfence();
            g_gen = old + 1u;
        } else {
            while (g_gen == old) { }
        }
        __threadfence();
    }
    __syncthreads();
}

// ---------------------------------------------------------------------------
// Preprocessing kernels (vectorized: float2 loads -> half2 stores; all K even)
// ---------------------------------------------------------------------------
__global__ void embed_f16(const int* __restrict__ tokens,
                          const float* __restrict__ emb,
                          __half* __restrict__ out)
{
    int tb = blockIdx.x;
    int tok = tokens[tb];
    const float2* src = (const float2*)(emb + (size_t)tok * EE);
    __half2* dst = (__half2*)(out + (size_t)tb * KP_E);
    for (int e = threadIdx.x; e < KP_E / 2; e += blockDim.x) {
        float2 v = (2 * e < EE) ? src[e] : make_float2(0.f, 0.f);
        dst[e] = __floats2half2_rn(v.x, v.y);
    }
}

__global__ void conv_emb(const float* __restrict__ emb, __half* __restrict__ out)
{
    int row = blockIdx.x;
    const float2* src = (const float2*)(emb + (size_t)row * EE);
    __half2* dst = (__half2*)(out + (size_t)row * KP_E);
    for (int e = threadIdx.x; e < KP_E / 2; e += blockDim.x) {
        float2 v = (2 * e < EE) ? src[e] : make_float2(0.f, 0.f);
        dst[e] = __floats2half2_rn(v.x, v.y);
    }
}

__global__ void reorder_f16(const float* __restrict__ W, __half* __restrict__ Wr,
                            int nh, int K, int Kp)
{
    int row = blockIdx.x;
    int j = row >> 2, g = row & 3;
    bool valid = (row < 4 * nh);
    const float2* src = (const float2*)(W + (size_t)(g * nh + j) * K);
    __half2* dst = (__half2*)(Wr + (size_t)row * Kp);
    for (int k = threadIdx.x; k < Kp / 2; k += blockDim.x) {
        float2 v = (valid && 2 * k < K) ? src[k] : make_float2(0.f, 0.f);
        dst[k] = __floats2half2_rn(v.x, v.y);
    }
}

__global__ void combine_bias(const float* __restrict__ b1, const float* __restrict__ b2,
                             float* __restrict__ br, int nh, int N4p)
{
    int r = blockIdx.x * blockDim.x + threadIdx.x;
    if (r < N4p) {
        int j = r >> 2, g = r & 3;
        br[r] = (r < 4 * nh) ? b1[g * nh + j] + b2[g * nh + j] : 0.0f;
    }
}

__global__ void conv_h0(const float* __restrict__ h0, __half* __restrict__ out,
                        int nh, int Kp)
{
    int b = blockIdx.x;
    const float2* src = (const float2*)(h0 + (size_t)b * nh);
    __half2* dst = (__half2*)(out + (size_t)b * Kp);
    for (int k = threadIdx.x; k < Kp / 2; k += blockDim.x) {
        float2 v = (2 * k < nh) ? src[k] : make_float2(0.f, 0.f);
        dst[k] = __floats2half2_rn(v.x, v.y);
    }
}

// ---------------------------------------------------------------------------
// FP16 GEMM (NT), 3-stage cp.async pipeline + ldmatrix operand fetch.
// C[m,n] = sum_k A[m,k]*B[n,k] + bias[n]
// Block 128x128, BK=32, 256 threads (8 warps 2m x 4n), warp tile 64x32.
// launch_bounds(256, 2): cap regs at 128 -> 2 CTAs/SM.
// ---------------------------------------------------------------------------
__global__ void __launch_bounds__(256, 2) gemm_f16(
    const __half* __restrict__ A, const __half* __restrict__ B,
    const float* __restrict__ bias, float* __restrict__ C,
    int N, int Kp, int lda, int ldb, int ldc)
{
    extern __shared__ __align__(16) char dsm[];
    __half* Asm = (__half*)dsm;              // 3 stages x 5120 halfs
    __half* Bsm = Asm + 3 * 5120;            // 3 stages x 5120 halfs

    int tid  = threadIdx.x;
    int warp = tid >> 5, lane = tid & 31;
    int wm = warp & 1, wn = warp >> 1;
    int g  = lane >> 2, tg = lane & 3;
    int m0 = blockIdx.y * 128;
    int n0 = blockIdx.x * 128;

    unsigned sA = (unsigned)__cvta_generic_to_shared(Asm);
    unsigned sB = (unsigned)__cvta_generic_to_shared(Bsm);

    // ldmatrix lane offsets
    int a_row = (lane & 7) + ((lane >> 3) & 1) * 8;
    int a_col = (lane >> 4) * 8;
    int b_row = (lane & 7) + (lane >> 4) * 8;
    int b_col = ((lane >> 3) & 1) * 8;

    int crow[2], cko[2];
    #pragma unroll
    for (int s = 0; s < 2; s++) {
        int c = tid + s * 256;
        crow[s] = c >> 2;
        cko[s]  = (c & 3) * 8;
    }

    float acc[4][4][4] = {};
    int nk = Kp >> 5;     // >= 13 always

#define ISSUE_AB(grp, stage) do {                                              \
        int _kt = (grp) << 5;                                                  \
        unsigned _so = (unsigned)(stage) * 10240u;                             \
        _Pragma("unroll")                                                      \
        for (int s = 0; s < 2; s++) {                                          \
            int row = crow[s], ko = cko[s];                                    \
            cp16(sA + _so + (row * 40 + ko) * 2,                               \
                 A + (size_t)(m0 + row) * lda + _kt + ko);                     \
            int gn = n0 + row;                                                 \
            int sz = (gn < N) ? 16 : 0;                                        \
            const __half* gb = B + (size_t)(gn < N ? gn : 0) * ldb + _kt + ko; \
            cp16z(sB + _so + (row * 40 + ko) * 2, gb, sz);                     \
        }                                                                      \
        cp_commit();                                                           \
    } while (0)

    ISSUE_AB(0, 0);
    ISSUE_AB(1, 1);

    for (int it = 0; it < nk; it++) {
        if (it + 2 <= nk) asm volatile("cp.async.wait_group 1;");
        else              asm volatile("cp.async.wait_group 0;");
        __syncthreads();
        if (it + 2 < nk) { int st = (it + 2) % 3; ISSUE_AB(it + 2, st); }

        unsigned ab = sA + (unsigned)(it % 3) * 10240u;
        unsigned bb = sB + (unsigned)(it % 3) * 10240u;
        #pragma unroll
        for (int kk = 0; kk < 32; kk += 16) {
            unsigned af[4][4], bf[4][2];
            #pragma unroll
            for (int i = 0; i < 4; i++) {
                int ar = wm * 64 + i * 16;
                ldsm_x4(af[i][0], af[i][1], af[i][2], af[i][3],
                        ab + (unsigned)(((ar + a_row) * 40 + kk + a_col) * 2));
            }
            #pragma unroll
            for (int j = 0; j < 4; j += 2) {
                int br = wn * 32 + j * 8;
                ldsm_x4(bf[j][0], bf[j][1], bf[j + 1][0], bf[j + 1][1],
                        bb + (unsigned)(((br + b_row) * 40 + kk + b_col) * 2));
            }
            #pragma unroll
            for (int i = 0; i < 4; i++)
                #pragma unroll
                for (int j = 0; j < 4; j++)
                    mma_f16(acc[i][j], af[i][0], af[i][1], af[i][2], af[i][3],
                            bf[j][0], bf[j][1]);
        }
    }
#undef ISSUE_AB

    #pragma unroll
    for (int i = 0; i < 4; i++) {
        int r0 = m0 + wm * 64 + i * 16 + g;
        #pragma unroll
        for (int j = 0; j < 4; j++) {
            int col = n0 + wn * 32 + j * 8 + 2 * tg;
            if (col < N) {
                float bz  = bias ? bias[col] : 0.0f;
                float bz1 = bias ? bias[col + 1] : 0.0f;
                float2 v0 = {acc[i][j][0] + bz, acc[i][j][1] + bz1};
                float2 v1 = {acc[i][j][2] + bz, acc[i][j][3] + bz1};
                *reinterpret_cast<float2*>(C + (size_t)r0 * ldc + col) = v0;
                *reinterpret_cast<float2*>(C + (size_t)(r0 + 8) * ldc + col) = v1;
            }
        }
    }
}

// ---------------------------------------------------------------------------
// Persistent LSTM recurrence, NTILE=32 gate-column tile, 2 CTAs/SM.
// 8 warps as 4m x 2n (warp 16x16). W slice resident in smem; h streamed per
// step (6-stage cp.async); xp prefetched into registers; grid barrier between
// steps. smem/CTA = 32*pitch*2 + 30720 + 8448 <= 113,408 B -> 2 resident
// CTAs/SM guaranteed (228.9 KB of 233.5 KB incl. 1KB/CTA reserve).
// ---------------------------------------------------------------------------
__global__ void __launch_bounds__(256, 2) lstm_persist32(
    const __half* __restrict__ h0f,
    const float*  __restrict__ c0,
    const __half* __restrict__ Wg,
    const float*  __restrict__ xproj,
    float* __restrict__ cbuf,
    __half* __restrict__ xout,
    int nh, int Kp, int N4p, int pitch, unsigned nblocks)
{
    extern __shared__ __align__(16) char dsm[];
    __half* Ws   = (__half*)dsm;                      // 32 x pitch
    __half* Hs   = Ws + 32 * pitch;                   // 6 stages x 2560
    float*  gates = (float*)(Hs + 6 * 2560);          // 64 x 33

    int tid  = threadIdx.x;
    int warp = tid >> 5, lane = tid & 31;
    int wm = warp >> 1;            // 0..3 (m)
    int wn = warp & 1;             // 0..1 (n)
    int n0 = blockIdx.x * 32;
    int b0 = blockIdx.y * 64;

    unsigned sW = (unsigned)__cvta_generic_to_shared(Ws);
    unsigned sH = (unsigned)__cvta_generic_to_shared(Hs);

    // ldmatrix lane offsets
    int a_row = (lane & 7) + ((lane >> 3) & 1) * 8;
    int a_col = (lane >> 4) * 8;
    int b_row = (lane & 7) + (lane >> 4) * 8;
    int b_col = ((lane >> 3) & 1) * 8;

    int kch = Kp >> 3;
    for (int c = tid; c < 32 * kch; c += 256) {
        int row = c / kch;
        int kc  = (c - row * kch) << 3;
        cp16(sW + (unsigned)(row * pitch + kc) * 2, Wg + (size_t)(n0 + row) * Kp + kc);
    }
    cp_commit();
    asm volatile("cp.async.wait_group 0;");
    __syncthreads();

    int nk   = Kp >> 5;
    int crow = tid >> 2;
    int cko  = (tid & 3) * 8;
    int jbase = n0 >> 2;

    for (int t = 0; t < TT; t++) {
        const __half* hsrc = t ? xout + (size_t)(t - 1) * BB * Kp : h0f;
        const float*  cin  = t ? cbuf + (size_t)((t - 1) & 1) * BB * HH : c0;
        float*  cout = cbuf + (size_t)(t & 1) * BB * HH;
        __half* yout = xout + (size_t)t * BB * Kp;
        const float* xp = xproj + (size_t)t * BB * N4p;

        // Prefetch xp for this step (independent of MMA; hides DRAM latency)
        float4 xv[2];
        #pragma unroll
        for (int s = 0; s < 2; s++) {
            int p  = tid + s * 256;
            int b  = p >> 3;
            int jl = p & 7;
            xv[s] = *reinterpret_cast<const float4*>(
                xp + (size_t)(b0 + b) * N4p + n0 + jl * 4);
        }

        float acc[2][4] = {};

#define ISSUE_H(grp, stage) do {                                           \
        cp16(sH + (unsigned)(stage) * 5120u + (crow * 40 + cko) * 2,       \
             hsrc + (size_t)(b0 + crow) * Kp + ((grp) << 5) + cko);        \
        cp_commit();                                                       \
    } while (0)

        ISSUE_H(0, 0); ISSUE_H(1, 1); ISSUE_H(2, 2);
        ISSUE_H(3, 3); ISSUE_H(4, 4);

        for (int it = 0; it < nk; it++) {
            if (it + 5 <= nk) asm volatile("cp.async.wait_group 4;");
            else              asm volatile("cp.async.wait_group 0;");
            __syncthreads();
            if (it + 5 < nk) { int st = (it + 5) % 6; ISSUE_H(it + 5, st); }

            unsigned ab = sH + (unsigned)(it % 6) * 5120u;
            int k0 = it << 5;
            #pragma unroll
            for (int kk = 0; kk < 32; kk += 16) {
                unsigned af[4], bf[2][2];
                {
                    int ar = wm * 16;
                    ldsm_x4(af[0], af[1], af[2], af[3],
                            ab + (unsigned)(((ar + a_row) * 40 + kk + a_col) * 2));
                }
                {
                    int br = wn * 16;
                    ldsm_x4(bf[0][0], bf[0][1], bf[1][0], bf[1][1],
                            sW + (unsigned)(((br + b_row) * pitch + k0 + kk + b_col) * 2));
                }
                #pragma unroll
                for (int j = 0; j < 2; j++)
                    mma_f16(acc[j], af[0], af[1], af[2], af[3],
                            bf[j][0], bf[j][1]);
            }
        }
#undef ISSUE_H

        int g  = lane >> 2, tg = lane & 3;
        {
            int r0 = wm * 16 + g;
            #pragma unroll
            for (int j = 0; j < 2; j++) {
                int col = wn * 16 + j * 8 + 2 * tg;
                gates[r0 * 33 + col]           = acc[j][0];
                gates[r0 * 33 + col + 1]       = acc[j][1];
                gates[(r0 + 8) * 33 + col]     = acc[j][2];
                gates[(r0 + 8) * 33 + col + 1] = acc[j][3];
            }
        }
        __syncthreads();

        #pragma unroll
        for (int s = 0; s < 2; s++) {
            int p  = tid + s * 256;
            int b  = p >> 3;
            int jl = p & 7;
            int j  = jbase + jl;
            if (j < nh) {
                int bg = b0 + b;
                float gi = gates[b * 33 + jl * 4 + 0] + xv[s].x;
                float gf = gates[b * 33 + jl * 4 + 1] + xv[s].y;
                float gg = gates[b * 33 + jl * 4 + 2] + xv[s].z;
                float go = gates[b * 33 + jl * 4 + 3] + xv[s].w;
                float iv = fsigmoid(gi);
                float fv = fsigmoid(gf);
                float gv = ftanh(gg);
                float ov = fsigmoid(go);
                float cv = fv * cin[(size_t)bg * nh + j] + iv * gv;
                float hv = ov * ftanh(cv);
                cout[(size_t)bg * nh + j] = cv;
                yout[(size_t)bg * Kp + j] = __float2half(hv);
            }
        }

        if (t + 1 < TT) grid_bar(nblocks);
    }
}

// ---------------------------------------------------------------------------
// Layer driver
// ---------------------------------------------------------------------------
static void run_layer(const __half* x_in, int Kp_in, int K_in, int nh, int Kp_h,
                      int N4p,
                      const float* W_ih, const float* W_hh,
                      const float* b_ih, const float* b_hh,
                      const float* h0, const float* c0,
                      __half* x_out,
                      __half* Wih, __half* Whh, float* bias,
                      float* xproj, float* cbuf, __half* h0f)
{
    reorder_f16<<<N4p, 256>>>(W_ih, Wih, nh, K_in, Kp_in);
    reorder_f16<<<N4p, 256>>>(W_hh, Whh, nh, nh, Kp_h);
    combine_bias<<<(N4p + 255) / 256, 256>>>(b_ih, b_hh, bias, nh, N4p);
    conv_h0<<<BB, 256>>>(h0, h0f, nh, Kp_h);

    // Input projection: xproj = x_in @ Wih^T + bias
    {
        dim3 grid(N4p / 128, (TT * BB) / 128);
        gemm_f16<<<grid, 256, 61440>>>(x_in, Wih, bias, xproj, N4p, Kp_in,
                                       Kp_in, Kp_in, N4p);
    }

    // Persistent recurrence (NTILE=32, 2 CTAs/SM): single launch, all steps
    {
        int pitch = Kp_h + 8;
        size_t smem = (size_t)32 * pitch * 2 + 6 * 2560 * 2 + 64 * 33 * 4;
        dim3 grid(N4p / 32, 2);
        unsigned nblocks = (N4p / 32) * 2;
        lstm_persist32<<<grid, 256, smem>>>(h0f, c0, Whh, xproj, cbuf, x_out,
                                            nh, Kp_h, N4p, pitch, nblocks);
    }
}

extern "C" void kernel_launch(void* const* d_in, const int* in_sizes, int n_in,
                              void* d_out, int out_size)
{
    const int*   tokens = (const int*)  d_in[0];
    const float* h0_0   = (const float*)d_in[1];
    const float* c0_0   = (const float*)d_in[2];
    const float* h0_1   = (const float*)d_in[3];
    const float* c0_1   = (const float*)d_in[4];
    const float* h0_2   = (const float*)d_in[5];
    const float* c0_2   = (const float*)d_in[6];
    const float* embw   = (const float*)d_in[7];
    const float* W_ih0  = (const float*)d_in[8];
    const float* W_hh0  = (const float*)d_in[9];
    const float* b_ih0  = (const float*)d_in[10];
    const float* b_hh0  = (const float*)d_in[11];
    const float* W_ih1  = (const float*)d_in[12];
    const float* W_hh1  = (const float*)d_in[13];
    const float* b_ih1  = (const float*)d_in[14];
    const float* b_hh1  = (const float*)d_in[15];
    const float* W_ih2  = (const float*)d_in[16];
    const float* W_hh2  = (const float*)d_in[17];
    const float* b_ih2  = (const float*)d_in[18];
    const float* b_hh2  = (const float*)d_in[19];
    const float* dec_b  = (const float*)d_in[20];
    float* logits = (float*)d_out;

    __half *x0, *x1, *x2, *x3, *embf, *Wih, *Whh, *h0f;
    float *bias, *xproj, *cbuf;
    cudaGetSymbolAddress((void**)&x0,    g_x0);
    cudaGetSymbolAddress((void**)&x1,    g_x1);
    cudaGetSymbolAddress((void**)&x2,    g_x2);
    cudaGetSymbolAddress((void**)&x3,    g_x3);
    cudaGetSymbolAddress((void**)&embf,  g_embf);
    cudaGetSymbolAddress((void**)&Wih,   g_Wih);
    cudaGetSymbolAddress((void**)&Whh,   g_Whh);
    cudaGetSymbolAddress((void**)&bias,  g_bias);
    cudaGetSymbolAddress((void**)&xproj, g_xproj);
    cudaGetSymbolAddress((void**)&cbuf,  g_c);
    cudaGetSymbolAddress((void**)&h0f,   g_h0f);

    cudaFuncSetAttribute(gemm_f16, cudaFuncAttributeMaxDynamicSharedMemorySize,
                         61440);
    cudaFuncSetAttribute(lstm_persist32,
                         cudaFuncAttributeMaxDynamicSharedMemorySize,
                         32 * (KP_H + 8) * 2 + 6 * 2560 * 2 + 64 * 33 * 4);

    // Preprocess: embedding gather + fp16 embedding table
    embed_f16<<<TT * BB, 256>>>(tokens, embw, x0);
    conv_emb<<<VV, 128>>>(embw, embf);

    // Three LSTM layers
    run_layer(x0, KP_E, EE, HH, KP_H, N4P_H, W_ih0, W_hh0, b_ih0, b_hh0,
              h0_0, c0_0, x1, Wih, Whh, bias, xproj, cbuf, h0f);
    run_layer(x1, KP_H, HH, HH, KP_H, N4P_H, W_ih1, W_hh1, b_ih1, b_hh1,
              h0_1, c0_1, x2, Wih, Whh, bias, xproj, cbuf, h0f);
    run_layer(x2, KP_H, HH, EE, KP_E, N4P_E, W_ih2, W_hh2, b_ih2, b_hh2,
              h0_2, c0_2, x3, Wih, Whh, bias, xproj, cbuf, h0f);

    // Tied decoder: logits = x3 @ embf^T + dec_b
    {
        dim3 grid((VV + 127) / 128, (TT * BB) / 128);
        gemm_f16<<<grid, 256, 61440>>>(x3, embf, dec_b, logits, VV, KP_E,
                                       KP_E, KP_E, VV);
    }
}

// round 14
// speedup vs baseline: 1.3345x; 1.0448x over previous
#include <cuda_runtime.h>
#include <cuda_fp16.h>
#include <math.h>
#include <stdint.h>

// Problem constants
#define TT 70
#define BB 128
#define EE 400
#define HH 1150
#define VV 33278

// Padded dims (K multiples of 32, strides 16B-aligned)
#define KP_E 416
#define KP_H 1152
#define N4P_H 4608
#define N4P_E 1664

// ---------------------------------------------------------------------------
// Scratch (device globals; zero-initialized at module load)
// ---------------------------------------------------------------------------
__device__ __half g_x0  [TT * BB * KP_E];
__device__ __half g_x1  [TT * BB * KP_H];
__device__ __half g_x2  [TT * BB * KP_H];
__device__ __half g_x3  [TT * BB * KP_E];
__device__ __half g_embf[VV * KP_E];
// Per-layer weight buffers (enable early prep on a side graph branch)
__device__ __half g_Wih0[N4P_H * KP_E];
__device__ __half g_Whh0[N4P_H * KP_H];
__device__ __half g_Wih1[N4P_H * KP_H];
__device__ __half g_Whh1[N4P_H * KP_H];
__device__ __half g_Wih2[N4P_E * KP_H];
__device__ __half g_Whh2[N4P_E * KP_E];
__device__ float  g_bias0[N4P_H];
__device__ float  g_bias1[N4P_H];
__device__ float  g_bias2[N4P_E];
__device__ __half g_h0f0[BB * KP_H];
__device__ __half g_h0f1[BB * KP_H];
__device__ __half g_h0f2[BB * KP_E];
__device__ __half g_xproj[TT * BB * N4P_H];   // fp16 x-projection
__device__ float  g_c   [2 * BB * HH];
__device__ unsigned g_count[2];               // per-batch-half barrier counters
__device__ volatile unsigned g_gen[2];        // per-batch-half generations

// ---------------------------------------------------------------------------
// PTX helpers
// ---------------------------------------------------------------------------
__device__ __forceinline__ void cp16(unsigned s, const void* g) {
    asm volatile("cp.async.cg.shared.global [%0], [%1], 16;" :: "r"(s), "l"(g));
}
__device__ __forceinline__ void cp16z(unsigned s, const void* g, int sz) {
    asm volatile("cp.async.cg.shared.global [%0], [%1], 16, %2;" :: "r"(s), "l"(g), "r"(sz));
}
__device__ __forceinline__ void cp_commit() {
    asm volatile("cp.async.commit_group;");
}
__device__ __forceinline__ void mma_f16(float c[4], unsigned a0, unsigned a1,
                                        unsigned a2, unsigned a3,
                                        unsigned b0, unsigned b1)
{
    asm("mma.sync.aligned.m16n8k16.row.col.f32.f16.f16.f32 "
        "{%0,%1,%2,%3},{%4,%5,%6,%7},{%8,%9},{%0,%1,%2,%3};"
        : "+f"(c[0]), "+f"(c[1]), "+f"(c[2]), "+f"(c[3])
        : "r"(a0), "r"(a1), "r"(a2), "r"(a3), "r"(b0), "r"(b1));
}
__device__ __forceinline__ void ldsm_x4(unsigned& r0, unsigned& r1,
                                        unsigned& r2, unsigned& r3, uint32_t a)
{
    asm volatile("ldmatrix.sync.aligned.m8n8.x4.shared.b16 {%0,%1,%2,%3}, [%4];"
                 : "=r"(r0), "=r"(r1), "=r"(r2), "=r"(r3) : "r"(a));
}
__device__ __forceinline__ float fsigmoid(float x) {
    return 1.0f / (1.0f + __expf(-x));
}
__device__ __forceinline__ float ftanh(float x) {
    return 2.0f / (1.0f + __expf(-2.0f * x)) - 1.0f;
}

// Per-half grid barrier (blocks sharing blockIdx.y only)
__device__ __forceinline__ void grid_bar(unsigned nblocks, int idx) {
    __syncthreads();
    if (threadIdx.x == 0) {
        unsigned old = g_gen[idx];
        __threadfence();
        unsigned t = atomicAdd(&g_count[idx], 1u);
        if (t == nblocks - 1u) {
            g_count[idx] = 0u;
            __threadfence();
            g_gen[idx] = old + 1u;
        } else {
            while (g_gen[idx] == old) { }
        }
        __threadfence();
    }
    __syncthreads();
}

// ---------------------------------------------------------------------------
// Preprocessing kernels (vectorized)
// ---------------------------------------------------------------------------
__global__ void embed_f16(const int* __restrict__ tokens,
                          const float* __restrict__ emb,
                          __half* __restrict__ out)
{
    int tb = blockIdx.x;
    int tok = tokens[tb];
    const float2* src = (const float2*)(emb + (size_t)tok * EE);
    __half2* dst = (__half2*)(out + (size_t)tb * KP_E);
    for (int e = threadIdx.x; e < KP_E / 2; e += blockDim.x) {
        float2 v = (2 * e < EE) ? src[e] : make_float2(0.f, 0.f);
        dst[e] = __floats2half2_rn(v.x, v.y);
    }
}

__global__ void conv_emb(const float* __restrict__ emb, __half* __restrict__ out)
{
    int row = blockIdx.x;
    const float2* src = (const float2*)(emb + (size_t)row * EE);
    __half2* dst = (__half2*)(out + (size_t)row * KP_E);
    for (int e = threadIdx.x; e < KP_E / 2; e += blockDim.x) {
        float2 v = (2 * e < EE) ? src[e] : make_float2(0.f, 0.f);
        dst[e] = __floats2half2_rn(v.x, v.y);
    }
}

__global__ void reorder_f16(const float* __restrict__ W, __half* __restrict__ Wr,
                            int nh, int K, int Kp)
{
    int row = blockIdx.x;
    int j = row >> 2, g = row & 3;
    bool valid = (row < 4 * nh);
    const float2* src = (const float2*)(W + (size_t)(g * nh + j) * K);
    __half2* dst = (__half2*)(Wr + (size_t)row * Kp);
    for (int k = threadIdx.x; k < Kp / 2; k += blockDim.x) {
        float2 v = (valid && 2 * k < K) ? src[k] : make_float2(0.f, 0.f);
        dst[k] = __floats2half2_rn(v.x, v.y);
    }
}

__global__ void combine_bias(const float* __restrict__ b1, const float* __restrict__ b2,
                             float* __restrict__ br, int nh, int N4p)
{
    int r = blockIdx.x * blockDim.x + threadIdx.x;
    if (r < N4p) {
        int j = r >> 2, g = r & 3;
        br[r] = (r < 4 * nh) ? b1[g * nh + j] + b2[g * nh + j] : 0.0f;
    }
}

__global__ void conv_h0(const float* __restrict__ h0, __half* __restrict__ out,
                        int nh, int Kp)
{
    int b = blockIdx.x;
    const float2* src = (const float2*)(h0 + (size_t)b * nh);
    __half2* dst = (__half2*)(out + (size_t)b * Kp);
    for (int k = threadIdx.x; k < Kp / 2; k += blockDim.x) {
        float2 v = (2 * k < nh) ? src[k] : make_float2(0.f, 0.f);
        dst[k] = __floats2half2_rn(v.x, v.y);
    }
}

// ---------------------------------------------------------------------------
// FP16 GEMM (NT), 3-stage cp.async pipeline + ldmatrix, 2 CTAs/SM.
// C[m,n] = sum_k A[m,k]*B[n,k] + bias[n]; out_half selects fp16/fp32 C.
// Block 128x128, BK=32, 256 threads (8 warps 2m x 4n), warp tile 64x32.
// ---------------------------------------------------------------------------
__global__ void __launch_bounds__(256, 2) gemm_f16(
    const __half* __restrict__ A, const __half* __restrict__ B,
    const float* __restrict__ bias, void* __restrict__ Cv, int out_half,
    int N, int Kp, int lda, int ldb, int ldc)
{
    extern __shared__ __align__(16) char dsm[];
    __half* Asm = (__half*)dsm;              // 3 stages x 5120 halfs
    __half* Bsm = Asm + 3 * 5120;            // 3 stages x 5120 halfs

    int tid  = threadIdx.x;
    int warp = tid >> 5, lane = tid & 31;
    int wm = warp & 1, wn = warp >> 1;
    int g  = lane >> 2, tg = lane & 3;
    int m0 = blockIdx.y * 128;
    int n0 = blockIdx.x * 128;

    unsigned sA = (unsigned)__cvta_generic_to_shared(Asm);
    unsigned sB = (unsigned)__cvta_generic_to_shared(Bsm);

    int a_row = (lane & 7) + ((lane >> 3) & 1) * 8;
    int a_col = (lane >> 4) * 8;
    int b_row = (lane & 7) + (lane >> 4) * 8;
    int b_col = ((lane >> 3) & 1) * 8;

    int crow[2], cko[2];
    #pragma unroll
    for (int s = 0; s < 2; s++) {
        int c = tid + s * 256;
        crow[s] = c >> 2;
        cko[s]  = (c & 3) * 8;
    }

    float acc[4][4][4] = {};
    int nk = Kp >> 5;

#define ISSUE_AB(grp, stage) do {                                              \
        int _kt = (grp) << 5;                                                  \
        unsigned _so = (unsigned)(stage) * 10240u;                             \
        _Pragma("unroll")                                                      \
        for (int s = 0; s < 2; s++) {                                          \
            int row = crow[s], ko = cko[s];                                    \
            cp16(sA + _so + (row * 40 + ko) * 2,                               \
                 A + (size_t)(m0 + row) * lda + _kt + ko);                     \
            int gn = n0 + row;                                                 \
            int sz = (gn < N) ? 16 : 0;                                        \
            const __half* gb = B + (size_t)(gn < N ? gn : 0) * ldb + _kt + ko; \
            cp16z(sB + _so + (row * 40 + ko) * 2, gb, sz);                     \
        }                                                                      \
        cp_commit();                                                           \
    } while (0)

    ISSUE_AB(0, 0);
    ISSUE_AB(1, 1);

    for (int it = 0; it < nk; it++) {
        if (it + 2 <= nk) asm volatile("cp.async.wait_group 1;");
        else              asm volatile("cp.async.wait_group 0;");
        __syncthreads();
        if (it + 2 < nk) { int st = (it + 2) % 3; ISSUE_AB(it + 2, st); }

        unsigned ab = sA + (unsigned)(it % 3) * 10240u;
        unsigned bb = sB + (unsigned)(it % 3) * 10240u;
        #pragma unroll
        for (int kk = 0; kk < 32; kk += 16) {
            unsigned af[4][4], bf[4][2];
            #pragma unroll
            for (int i = 0; i < 4; i++) {
                int ar = wm * 64 + i * 16;
                ldsm_x4(af[i][0], af[i][1], af[i][2], af[i][3],
                        ab + (unsigned)(((ar + a_row) * 40 + kk + a_col) * 2));
            }
            #pragma unroll
            for (int j = 0; j < 4; j += 2) {
                int br = wn * 32 + j * 8;
                ldsm_x4(bf[j][0], bf[j][1], bf[j + 1][0], bf[j + 1][1],
                        bb + (unsigned)(((br + b_row) * 40 + kk + b_col) * 2));
            }
            #pragma unroll
            for (int i = 0; i < 4; i++)
                #pragma unroll
                for (int j = 0; j < 4; j++)
                    mma_f16(acc[i][j], af[i][0], af[i][1], af[i][2], af[i][3],
                            bf[j][0], bf[j][1]);
        }
    }
#undef ISSUE_AB

    #pragma unroll
    for (int i = 0; i < 4; i++) {
        int r0 = m0 + wm * 64 + i * 16 + g;
        #pragma unroll
        for (int j = 0; j < 4; j++) {
            int col = n0 + wn * 32 + j * 8 + 2 * tg;
            if (col < N) {
                float bz  = bias ? bias[col] : 0.0f;
                float bz1 = bias ? bias[col + 1] : 0.0f;
                float v00 = acc[i][j][0] + bz, v01 = acc[i][j][1] + bz1;
                float v10 = acc[i][j][2] + bz, v11 = acc[i][j][3] + bz1;
                if (out_half) {
                    __half* Ch = (__half*)Cv;
                    *reinterpret_cast<__half2*>(Ch + (size_t)r0 * ldc + col) =
                        __floats2half2_rn(v00, v01);
                    *reinterpret_cast<__half2*>(Ch + (size_t)(r0 + 8) * ldc + col) =
                        __floats2half2_rn(v10, v11);
                } else {
                    float* Cf = (float*)Cv;
                    float2 a = {v00, v01}, b = {v10, v11};
                    *reinterpret_cast<float2*>(Cf + (size_t)r0 * ldc + col) = a;
                    *reinterpret_cast<float2*>(Cf + (size_t)(r0 + 8) * ldc + col) = b;
                }
            }
        }
    }
}

// ---------------------------------------------------------------------------
// Persistent LSTM recurrence, NTILE=32 tile, 2 CTAs/SM, steps [t0, t1).
// xp is fp16; per-batch-half grid barrier.
// ---------------------------------------------------------------------------
__global__ void __launch_bounds__(256, 2) lstm_persist32(
    const __half* __restrict__ h0f,
    const float*  __restrict__ c0,
    const __half* __restrict__ Wg,
    const __half* __restrict__ xproj,
    float* __restrict__ cbuf,
    __half* __restrict__ xout,
    int nh, int Kp, int N4p, int pitch, unsigned nblocks, int t0, int t1)
{
    extern __shared__ __align__(16) char dsm[];
    __half* Ws   = (__half*)dsm;                      // 32 x pitch
    __half* Hs   = Ws + 32 * pitch;                   // 6 stages x 2560
    float*  gates = (float*)(Hs + 6 * 2560);          // 64 x 33

    int tid  = threadIdx.x;
    int warp = tid >> 5, lane = tid & 31;
    int wm = warp >> 1;
    int wn = warp & 1;
    int n0 = blockIdx.x * 32;
    int b0 = blockIdx.y * 64;

    unsigned sW = (unsigned)__cvta_generic_to_shared(Ws);
    unsigned sH = (unsigned)__cvta_generic_to_shared(Hs);

    int a_row = (lane & 7) + ((lane >> 3) & 1) * 8;
    int a_col = (lane >> 4) * 8;
    int b_row = (lane & 7) + (lane >> 4) * 8;
    int b_col = ((lane >> 3) & 1) * 8;

    int kch = Kp >> 3;
    for (int c = tid; c < 32 * kch; c += 256) {
        int row = c / kch;
        int kc  = (c - row * kch) << 3;
        cp16(sW + (unsigned)(row * pitch + kc) * 2, Wg + (size_t)(n0 + row) * Kp + kc);
    }
    cp_commit();
    asm volatile("cp.async.wait_group 0;");
    __syncthreads();

    int nk   = Kp >> 5;
    int crow = tid >> 2;
    int cko  = (tid & 3) * 8;
    int jbase = n0 >> 2;

    for (int t = t0; t < t1; t++) {
        const __half* hsrc = t ? xout + (size_t)(t - 1) * BB * Kp : h0f;
        const float*  cin  = t ? cbuf + (size_t)((t - 1) & 1) * BB * HH : c0;
        float*  cout = cbuf + (size_t)(t & 1) * BB * HH;
        __half* yout = xout + (size_t)t * BB * Kp;
        const __half* xp = xproj + (size_t)t * BB * N4p;

        // Prefetch xp (fp16) for this step
        uint2 xr[2];
        #pragma unroll
        for (int s = 0; s < 2; s++) {
            int p  = tid + s * 256;
            int b  = p >> 3;
            int jl = p & 7;
            xr[s] = *reinterpret_cast<const uint2*>(
                xp + (size_t)(b0 + b) * N4p + n0 + jl * 4);
        }

        float acc[2][4] = {};

#define ISSUE_H(grp, stage) do {                                           \
        cp16(sH + (unsigned)(stage) * 5120u + (crow * 40 + cko) * 2,       \
             hsrc + (size_t)(b0 + crow) * Kp + ((grp) << 5) + cko);        \
        cp_commit();                                                       \
    } while (0)

        ISSUE_H(0, 0); ISSUE_H(1, 1); ISSUE_H(2, 2);
        ISSUE_H(3, 3); ISSUE_H(4, 4);

        for (int it = 0; it < nk; it++) {
            if (it + 5 <= nk) asm volatile("cp.async.wait_group 4;");
            else              asm volatile("cp.async.wait_group 0;");
            __syncthreads();
            if (it + 5 < nk) { int st = (it + 5) % 6; ISSUE_H(it + 5, st); }

            unsigned ab = sH + (unsigned)(it % 6) * 5120u;
            int k0 = it << 5;
            #pragma unroll
            for (int kk = 0; kk < 32; kk += 16) {
                unsigned af[4], bf[2][2];
                {
                    int ar = wm * 16;
                    ldsm_x4(af[0], af[1], af[2], af[3],
                            ab + (unsigned)(((ar + a_row) * 40 + kk + a_col) * 2));
                }
                {
                    int br = wn * 16;
                    ldsm_x4(bf[0][0], bf[0][1], bf[1][0], bf[1][1],
                            sW + (unsigned)(((br + b_row) * pitch + k0 + kk + b_col) * 2));
                }
                #pragma unroll
                for (int j = 0; j < 2; j++)
                    mma_f16(acc[j], af[0], af[1], af[2], af[3],
                            bf[j][0], bf[j][1]);
            }
        }
#undef ISSUE_H

        int g  = lane >> 2, tg = lane & 3;
        {
            int r0 = wm * 16 + g;
            #pragma unroll
            for (int j = 0; j < 2; j++) {
                int col = wn * 16 + j * 8 + 2 * tg;
                gates[r0 * 33 + col]           = acc[j][0];
                gates[r0 * 33 + col + 1]       = acc[j][1];
                gates[(r0 + 8) * 33 + col]     = acc[j][2];
                gates[(r0 + 8) * 33 + col + 1] = acc[j][3];
            }
        }
        __syncthreads();

        #pragma unroll
        for (int s = 0; s < 2; s++) {
            int p  = tid + s * 256;
            int b  = p >> 3;
            int jl = p & 7;
            int j  = jbase + jl;
            if (j < nh) {
                int bg = b0 + b;
                __half2 x01 = *reinterpret_cast<__half2*>(&xr[s].x);
                __half2 x23 = *reinterpret_cast<__half2*>(&xr[s].y);
                float2 f01 = __half22float2(x01);
                float2 f23 = __half22float2(x23);
                float gi = gates[b * 33 + jl * 4 + 0] + f01.x;
                float gf = gates[b * 33 + jl * 4 + 1] + f01.y;
                float gg = gates[b * 33 + jl * 4 + 2] + f23.x;
                float go = gates[b * 33 + jl * 4 + 3] + f23.y;
                float iv = fsigmoid(gi);
                float fv = fsigmoid(gf);
                float gv = ftanh(gg);
                float ov = fsigmoid(go);
                float cv = fv * cin[(size_t)bg * nh + j] + iv * gv;
                float hv = ov * ftanh(cv);
                cout[(size_t)bg * nh + j] = cv;
                yout[(size_t)bg * Kp + j] = __float2half(hv);
            }
        }

        if (t + 1 < t1) grid_bar(nblocks, blockIdx.y);
    }
}

// ---------------------------------------------------------------------------
// Host-side helpers
// ---------------------------------------------------------------------------
static void prep_layer(cudaStream_t st,
                       const float* W_ih, const float* W_hh,
                       const float* b_ih, const float* b_hh, const float* h0,
                       __half* Wih, __half* Whh, float* bias, __half* h0f,
                       int nh, int K_in, int Kp_in, int Kp_h, int N4p)
{
    reorder_f16<<<N4p, 256, 0, st>>>(W_ih, Wih, nh, K_in, Kp_in);
    reorder_f16<<<N4p, 256, 0, st>>>(W_hh, Whh, nh, nh, Kp_h);
    combine_bias<<<(N4p + 255) / 256, 256, 0, st>>>(b_ih, b_hh, bias, nh, N4p);
    conv_h0<<<BB, 256, 0, st>>>(h0, h0f, nh, Kp_h);
}

static void run_proj(const __half* x_in, const __half* Wih, const float* bias,
                     __half* xproj, int N4p, int Kp_in)
{
    dim3 grid(N4p / 128, (TT * BB) / 128);
    gemm_f16<<<grid, 256, 61440>>>(x_in, Wih, bias, xproj, 1, N4p, Kp_in,
                                   Kp_in, Kp_in, N4p);
}

static void run_rec(const __half* h0f, const float* c0, const __half* Whh,
                    const __half* xproj, float* cbuf, __half* x_out,
                    int nh, int Kp_h, int N4p, int t0, int t1)
{
    int pitch = Kp_h + 8;
    size_t smem = (size_t)32 * pitch * 2 + 6 * 2560 * 2 + 64 * 33 * 4;
    dim3 grid(N4p / 32, 2);
    unsigned nb = N4p / 32;   // per-half arrival count
    lstm_persist32<<<grid, 256, smem>>>(h0f, c0, Whh, xproj, cbuf, x_out,
                                        nh, Kp_h, N4p, pitch, nb, t0, t1);
}

extern "C" void kernel_launch(void* const* d_in, const int* in_sizes, int n_in,
                              void* d_out, int out_size)
{
    const int*   tokens = (const int*)  d_in[0];
    const float* h0_0   = (const float*)d_in[1];
    const float* c0_0   = (const float*)d_in[2];
    const float* h0_1   = (const float*)d_in[3];
    const float* c0_1   = (const float*)d_in[4];
    const float* h0_2   = (const float*)d_in[5];
    const float* c0_2   = (const float*)d_in[6];
    const float* embw   = (const float*)d_in[7];
    const float* W_ih0  = (const float*)d_in[8];
    const float* W_hh0  = (const float*)d_in[9];
    const float* b_ih0  = (const float*)d_in[10];
    const float* b_hh0  = (const float*)d_in[11];
    const float* W_ih1  = (const float*)d_in[12];
    const float* W_hh1  = (const float*)d_in[13];
    const float* b_ih1  = (const float*)d_in[14];
    const float* b_hh1  = (const float*)d_in[15];
    const float* W_ih2  = (const float*)d_in[16];
    const float* W_hh2  = (const float*)d_in[17];
    const float* b_ih2  = (const float*)d_in[18];
    const float* b_hh2  = (const float*)d_in[19];
    const float* dec_b  = (const float*)d_in[20];
    float* logits = (float*)d_out;

    __half *x0, *x1, *x2, *x3, *embf, *xproj, *h0f0, *h0f1, *h0f2;
    __half *Wih0, *Whh0, *Wih1, *Whh1, *Wih2, *Whh2;
    float *bias0, *bias1, *bias2, *cbuf;
    cudaGetSymbolAddress((void**)&x0,    g_x0);
    cudaGetSymbolAddress((void**)&x1,    g_x1);
    cudaGetSymbolAddress((void**)&x2,    g_x2);
    cudaGetSymbolAddress((void**)&x3,    g_x3);
    cudaGetSymbolAddress((void**)&embf,  g_embf);
    cudaGetSymbolAddress((void**)&Wih0,  g_Wih0);
    cudaGetSymbolAddress((void**)&Whh0,  g_Whh0);
    cudaGetSymbolAddress((void**)&Wih1,  g_Wih1);
    cudaGetSymbolAddress((void**)&Whh1,  g_Whh1);
    cudaGetSymbolAddress((void**)&Wih2,  g_Wih2);
    cudaGetSymbolAddress((void**)&Whh2,  g_Whh2);
    cudaGetSymbolAddress((void**)&bias0, g_bias0);
    cudaGetSymbolAddress((void**)&bias1, g_bias1);
    cudaGetSymbolAddress((void**)&bias2, g_bias2);
    cudaGetSymbolAddress((void**)&h0f0,  g_h0f0);
    cudaGetSymbolAddress((void**)&h0f1,  g_h0f1);
    cudaGetSymbolAddress((void**)&h0f2,  g_h0f2);
    cudaGetSymbolAddress((void**)&xproj, g_xproj);
    cudaGetSymbolAddress((void**)&cbuf,  g_c);

    cudaFuncSetAttribute(gemm_f16, cudaFuncAttributeMaxDynamicSharedMemorySize,
                         61440);
    cudaFuncSetAttribute(lstm_persist32,
                         cudaFuncAttributeMaxDynamicSharedMemorySize,
                         32 * (KP_H + 8) * 2 + 6 * 2560 * 2 + 64 * 33 * 4);

    // One-time stream/event resources (identical work every call)
    static cudaStream_t s_side = 0;
    static cudaEvent_t eFork = 0, ePrep = 0, eMid = 0, eDec = 0;
    if (!s_side) {
        cudaStreamCreateWithFlags(&s_side, cudaStreamNonBlocking);
        cudaEventCreateWithFlags(&eFork, cudaEventDisableTiming);
        cudaEventCreateWithFlags(&ePrep, cudaEventDisableTiming);
        cudaEventCreateWithFlags(&eMid,  cudaEventDisableTiming);
        cudaEventCreateWithFlags(&eDec,  cudaEventDisableTiming);
    }

    // Fork: side branch does decoder-table conversion + layer-1/2 prep,
    // overlapping layer-0 projection/recurrence on the main branch.
    cudaEventRecord(eFork, 0);
    cudaStreamWaitEvent(s_side, eFork, 0);

    conv_emb<<<VV, 128, 0, s_side>>>(embw, embf);
    prep_layer(s_side, W_ih1, W_hh1, b_ih1, b_hh1, h0_1,
               Wih1, Whh1, bias1, h0f1, HH, HH, KP_H, KP_H, N4P_H);
    prep_layer(s_side, W_ih2, W_hh2, b_ih2, b_hh2, h0_2,
               Wih2, Whh2, bias2, h0f2, EE, HH, KP_H, KP_E, N4P_E);
    cudaEventRecord(ePrep, s_side);

    // Main branch: layer 0
    prep_layer(0, W_ih0, W_hh0, b_ih0, b_hh0, h0_0,
               Wih0, Whh0, bias0, h0f0, HH, EE, KP_E, KP_H, N4P_H);
    embed_f16<<<TT * BB, 256>>>(tokens, embw, x0);
    run_proj(x0, Wih0, bias0, xproj, N4P_H, KP_E);
    run_rec(h0f0, c0_0, Whh0, xproj, cbuf, x1, HH, KP_H, N4P_H, 0, TT);

    // Join side prep; layers 1 and 2
    cudaStreamWaitEvent(0, ePrep, 0);
    run_proj(x1, Wih1, bias1, xproj, N4P_H, KP_H);
    run_rec(h0f1, c0_1, Whh1, xproj, cbuf, x2, HH, KP_H, N4P_H, 0, TT);

    run_proj(x2, Wih2, bias2, xproj, N4P_E, KP_H);
    run_rec(h0f2, c0_2, Whh2, xproj, cbuf, x3, EE, KP_E, N4P_E, 0, 35);
    cudaEventRecord(eMid, 0);

    // Main branch continues: recurrence part 2 (enqueued first for priority)
    run_rec(h0f2, c0_2, Whh2, xproj, cbuf, x3, EE, KP_E, N4P_E, 35, TT);

    // Side branch: decoder chunk 1 (rows t<35) concurrent with rec part 2
    cudaStreamWaitEvent(s_side, eMid, 0);
    {
        dim3 grid((VV + 127) / 128, 35);
        gemm_f16<<<grid, 256, 61440, s_side>>>(x3, embf, dec_b, logits, 0,
                                               VV, KP_E, KP_E, KP_E, VV);
    }
    cudaEventRecord(eDec, s_side);

    // Main branch: decoder chunk 2 (rows t>=35), then join
    {
        dim3 grid((VV + 127) / 128, 35);
        gemm_f16<<<grid, 256, 61440>>>(x3 + (size_t)4480 * KP_E, embf, dec_b,
                                       logits + (size_t)4480 * VV, 0,
                                       VV, KP_E, KP_E, KP_E, VV);
    }
    cudaStreamWaitEvent(0, eDec, 0);
}

// round 15
// speedup vs baseline: 1.3597x; 1.0189x over previous
#include <cuda_runtime.h>
#include <cuda_fp16.h>
#include <math.h>
#include <stdint.h>

// Problem constants
#define TT 70
#define BB 128
#define EE 400
#define HH 1150
#define VV 33278

// Padded dims (K multiples of 64 for GEMM BK; strides 16B-aligned)
#define KP_E 448
#define KP_H 1152
#define N4P_H 4608
#define N4P_E 1664

// ---------------------------------------------------------------------------
// Scratch (device globals; zero-initialized at module load)
// ---------------------------------------------------------------------------
__device__ __half g_x0  [TT * BB * KP_E];
__device__ __half g_x1  [TT * BB * KP_H];
__device__ __half g_x2  [TT * BB * KP_H];
__device__ __half g_x3  [TT * BB * KP_E];
__device__ __half g_embf[VV * KP_E];
__device__ __half g_Wih0[N4P_H * KP_E];
__device__ __half g_Whh0[N4P_H * KP_H];
__device__ __half g_Wih1[N4P_H * KP_H];
__device__ __half g_Whh1[N4P_H * KP_H];
__device__ __half g_Wih2[N4P_E * KP_H];
__device__ __half g_Whh2[N4P_E * KP_E];
__device__ float  g_bias0[N4P_H];
__device__ float  g_bias1[N4P_H];
__device__ float  g_bias2[N4P_E];
__device__ __half g_h0f0[BB * KP_H];
__device__ __half g_h0f1[BB * KP_H];
__device__ __half g_h0f2[BB * KP_E];
__device__ __half g_xproj[TT * BB * N4P_H];   // fp16 x-projection
__device__ float  g_c   [2 * BB * HH];
__device__ unsigned g_count[2];               // per-batch-half barrier counters
__device__ volatile unsigned g_gen[2];        // per-batch-half generations

// ---------------------------------------------------------------------------
// PTX helpers
// ---------------------------------------------------------------------------
__device__ __forceinline__ void cp16(unsigned s, const void* g) {
    asm volatile("cp.async.cg.shared.global [%0], [%1], 16;" :: "r"(s), "l"(g));
}
__device__ __forceinline__ void cp16z(unsigned s, const void* g, int sz) {
    asm volatile("cp.async.cg.shared.global [%0], [%1], 16, %2;" :: "r"(s), "l"(g), "r"(sz));
}
__device__ __forceinline__ void cp_commit() {
    asm volatile("cp.async.commit_group;");
}
__device__ __forceinline__ void mma_f16(float c[4], unsigned a0, unsigned a1,
                                        unsigned a2, unsigned a3,
                                        unsigned b0, unsigned b1)
{
    asm("mma.sync.aligned.m16n8k16.row.col.f32.f16.f16.f32 "
        "{%0,%1,%2,%3},{%4,%5,%6,%7},{%8,%9},{%0,%1,%2,%3};"
        : "+f"(c[0]), "+f"(c[1]), "+f"(c[2]), "+f"(c[3])
        : "r"(a0), "r"(a1), "r"(a2), "r"(a3), "r"(b0), "r"(b1));
}
__device__ __forceinline__ void ldsm_x4(unsigned& r0, unsigned& r1,
                                        unsigned& r2, unsigned& r3, uint32_t a)
{
    asm volatile("ldmatrix.sync.aligned.m8n8.x4.shared.b16 {%0,%1,%2,%3}, [%4];"
                 : "=r"(r0), "=r"(r1), "=r"(r2), "=r"(r3) : "r"(a));
}
__device__ __forceinline__ float fsigmoid(float x) {
    return 1.0f / (1.0f + __expf(-x));
}
__device__ __forceinline__ float ftanh(float x) {
    return 2.0f / (1.0f + __expf(-2.0f * x)) - 1.0f;
}

// Per-half grid barrier
__device__ __forceinline__ void grid_bar(unsigned nblocks, int idx) {
    __syncthreads();
    if (threadIdx.x == 0) {
        unsigned old = g_gen[idx];
        __threadfence();
        unsigned t = atomicAdd(&g_count[idx], 1u);
        if (t == nblocks - 1u) {
            g_count[idx] = 0u;
            __threadfence();
            g_gen[idx] = old + 1u;
        } else {
            while (g_gen[idx] == old) { }
        }
        __threadfence();
    }
    __syncthreads();
}

// ---------------------------------------------------------------------------
// Preprocessing kernels (vectorized)
// ---------------------------------------------------------------------------
__global__ void embed_f16(const int* __restrict__ tokens,
                          const float* __restrict__ emb,
                          __half* __restrict__ out)
{
    int tb = blockIdx.x;
    int tok = tokens[tb];
    const float2* src = (const float2*)(emb + (size_t)tok * EE);
    __half2* dst = (__half2*)(out + (size_t)tb * KP_E);
    for (int e = threadIdx.x; e < KP_E / 2; e += blockDim.x) {
        float2 v = (2 * e < EE) ? src[e] : make_float2(0.f, 0.f);
        dst[e] = __floats2half2_rn(v.x, v.y);
    }
}

__global__ void conv_emb(const float* __restrict__ emb, __half* __restrict__ out)
{
    int row = blockIdx.x;
    const float2* src = (const float2*)(emb + (size_t)row * EE);
    __half2* dst = (__half2*)(out + (size_t)row * KP_E);
    for (int e = threadIdx.x; e < KP_E / 2; e += blockDim.x) {
        float2 v = (2 * e < EE) ? src[e] : make_float2(0.f, 0.f);
        dst[e] = __floats2half2_rn(v.x, v.y);
    }
}

__global__ void reorder_f16(const float* __restrict__ W, __half* __restrict__ Wr,
                            int nh, int K, int Kp)
{
    int row = blockIdx.x;
    int j = row >> 2, g = row & 3;
    bool valid = (row < 4 * nh);
    const float2* src = (const float2*)(W + (size_t)(g * nh + j) * K);
    __half2* dst = (__half2*)(Wr + (size_t)row * Kp);
    for (int k = threadIdx.x; k < Kp / 2; k += blockDim.x) {
        float2 v = (valid && 2 * k < K) ? src[k] : make_float2(0.f, 0.f);
        dst[k] = __floats2half2_rn(v.x, v.y);
    }
}

__global__ void combine_bias(const float* __restrict__ b1, const float* __restrict__ b2,
                             float* __restrict__ br, int nh, int N4p)
{
    int r = blockIdx.x * blockDim.x + threadIdx.x;
    if (r < N4p) {
        int j = r >> 2, g = r & 3;
        br[r] = (r < 4 * nh) ? b1[g * nh + j] + b2[g * nh + j] : 0.0f;
    }
}

__global__ void conv_h0(const float* __restrict__ h0, __half* __restrict__ out,
                        int nh, int Kp)
{
    int b = blockIdx.x;
    const float2* src = (const float2*)(h0 + (size_t)b * nh);
    __half2* dst = (__half2*)(out + (size_t)b * Kp);
    for (int k = threadIdx.x; k < Kp / 2; k += blockDim.x) {
        float2 v = (2 * k < nh) ? src[k] : make_float2(0.f, 0.f);
        dst[k] = __floats2half2_rn(v.x, v.y);
    }
}

// ---------------------------------------------------------------------------
// FP16 GEMM (NT), BK=64, 3-stage cp.async pipeline + ldmatrix, 2 CTAs/SM.
// C[m,n] = sum_k A[m,k]*B[n,k] + bias[n]; out_half selects fp16/fp32 C.
// Block 128x128, 256 threads (8 warps 2m x 4n), warp tile 64x32.
// smem: pitch 72 halfs; stage = 128*72*2 = 18432 B; total 6*18432 = 110592 B.
// Kp must be a multiple of 64 (448 or 1152).
// ---------------------------------------------------------------------------
__global__ void __launch_bounds__(256, 2) gemm_f16(
    const __half* __restrict__ A, const __half* __restrict__ B,
    const float* __restrict__ bias, void* __restrict__ Cv, int out_half,
    int N, int Kp, int lda, int ldb, int ldc)
{
    extern __shared__ __align__(16) char dsm[];
    unsigned sA = (unsigned)__cvta_generic_to_shared(dsm);        // 3 x 18432 B
    unsigned sB = sA + 3u * 18432u;                               // 3 x 18432 B

    int tid  = threadIdx.x;
    int warp = tid >> 5, lane = tid & 31;
    int wm = warp & 1, wn = warp >> 1;
    int g  = lane >> 2, tg = lane & 3;
    int m0 = blockIdx.y * 128;
    int n0 = blockIdx.x * 128;

    int a_row = (lane & 7) + ((lane >> 3) & 1) * 8;
    int a_col = (lane >> 4) * 8;
    int b_row = (lane & 7) + (lane >> 4) * 8;
    int b_col = ((lane >> 3) & 1) * 8;

    // chunk mapping: 1024 16B-chunks per matrix per stage; 4 per thread
    int crow[4], cko[4];
    #pragma unroll
    for (int s = 0; s < 4; s++) {
        int c = tid + s * 256;
        crow[s] = c >> 3;            // 0..127
        cko[s]  = (c & 7) * 8;       // 0..56 halfs
    }

    float acc[4][4][4] = {};
    int nk = Kp >> 6;                // 7 or 18

#define ISSUE_AB(grp, stage) do {                                              \
        int _kt = (grp) << 6;                                                  \
        unsigned _so = (unsigned)(stage) * 18432u;                             \
        _Pragma("unroll")                                                      \
        for (int s = 0; s < 4; s++) {                                          \
            int row = crow[s], ko = cko[s];                                    \
            cp16(sA + _so + (unsigned)((row * 72 + ko) * 2),                   \
                 A + (size_t)(m0 + row) * lda + _kt + ko);                     \
            int gn = n0 + row;                                                 \
            int sz = (gn < N) ? 16 : 0;                                        \
            const __half* gb = B + (size_t)(gn < N ? gn : 0) * ldb + _kt + ko; \
            cp16z(sB + _so + (unsigned)((row * 72 + ko) * 2), gb, sz);         \
        }                                                                      \
        cp_commit();                                                           \
    } while (0)

    ISSUE_AB(0, 0);
    ISSUE_AB(1, 1);

    for (int it = 0; it < nk; it++) {
        if (it + 2 <= nk) asm volatile("cp.async.wait_group 1;");
        else              asm volatile("cp.async.wait_group 0;");
        __syncthreads();
        if (it + 2 < nk) { int st = (it + 2) % 3; ISSUE_AB(it + 2, st); }

        unsigned ab = sA + (unsigned)(it % 3) * 18432u;
        unsigned bb = sB + (unsigned)(it % 3) * 18432u;
        #pragma unroll
        for (int kk = 0; kk < 64; kk += 16) {
            unsigned af[4][4], bf[4][2];
            #pragma unroll
            for (int i = 0; i < 4; i++) {
                int ar = wm * 64 + i * 16;
                ldsm_x4(af[i][0], af[i][1], af[i][2], af[i][3],
                        ab + (unsigned)(((ar + a_row) * 72 + kk + a_col) * 2));
            }
            #pragma unroll
            for (int j = 0; j < 4; j += 2) {
                int br = wn * 32 + j * 8;
                ldsm_x4(bf[j][0], bf[j][1], bf[j + 1][0], bf[j + 1][1],
                        bb + (unsigned)(((br + b_row) * 72 + kk + b_col) * 2));
            }
            #pragma unroll
            for (int i = 0; i < 4; i++)
                #pragma unroll
                for (int j = 0; j < 4; j++)
                    mma_f16(acc[i][j], af[i][0], af[i][1], af[i][2], af[i][3],
                            bf[j][0], bf[j][1]);
        }
    }
#undef ISSUE_AB

    #pragma unroll
    for (int i = 0; i < 4; i++) {
        int r0 = m0 + wm * 64 + i * 16 + g;
        #pragma unroll
        for (int j = 0; j < 4; j++) {
            int col = n0 + wn * 32 + j * 8 + 2 * tg;
            if (col < N) {
                float bz  = bias ? bias[col] : 0.0f;
                float bz1 = bias ? bias[col + 1] : 0.0f;
                float v00 = acc[i][j][0] + bz, v01 = acc[i][j][1] + bz1;
                float v10 = acc[i][j][2] + bz, v11 = acc[i][j][3] + bz1;
                if (out_half) {
                    __half* Ch = (__half*)Cv;
                    *reinterpret_cast<__half2*>(Ch + (size_t)r0 * ldc + col) =
                        __floats2half2_rn(v00, v01);
                    *reinterpret_cast<__half2*>(Ch + (size_t)(r0 + 8) * ldc + col) =
                        __floats2half2_rn(v10, v11);
                } else {
                    float* Cf = (float*)Cv;
                    float2 a = {v00, v01}, b = {v10, v11};
                    *reinterpret_cast<float2*>(Cf + (size_t)r0 * ldc + col) = a;
                    *reinterpret_cast<float2*>(Cf + (size_t)(r0 + 8) * ldc + col) = b;
                }
            }
        }
    }
}

// ---------------------------------------------------------------------------
// Persistent LSTM recurrence, NTILE=32 tile, 2 CTAs/SM, steps [t0, t1).
// xp is fp16; per-batch-half grid barrier. (BK=32 — loop is latency-bound.)
// ---------------------------------------------------------------------------
__global__ void __launch_bounds__(256, 2) lstm_persist32(
    const __half* __restrict__ h0f,
    const float*  __restrict__ c0,
    const __half* __restrict__ Wg,
    const __half* __restrict__ xproj,
    float* __restrict__ cbuf,
    __half* __restrict__ xout,
    int nh, int Kp, int N4p, int pitch, unsigned nblocks, int t0, int t1)
{
    extern __shared__ __align__(16) char dsm[];
    __half* Ws   = (__half*)dsm;                      // 32 x pitch
    __half* Hs   = Ws + 32 * pitch;                   // 6 stages x 2560
    float*  gates = (float*)(Hs + 6 * 2560);          // 64 x 33

    int tid  = threadIdx.x;
    int warp = tid >> 5, lane = tid & 31;
    int wm = warp >> 1;
    int wn = warp & 1;
    int n0 = blockIdx.x * 32;
    int b0 = blockIdx.y * 64;

    unsigned sW = (unsigned)__cvta_generic_to_shared(Ws);
    unsigned sH = (unsigned)__cvta_generic_to_shared(Hs);

    int a_row = (lane & 7) + ((lane >> 3) & 1) * 8;
    int a_col = (lane >> 4) * 8;
    int b_row = (lane & 7) + (lane >> 4) * 8;
    int b_col = ((lane >> 3) & 1) * 8;

    int kch = Kp >> 3;
    for (int c = tid; c < 32 * kch; c += 256) {
        int row = c / kch;
        int kc  = (c - row * kch) << 3;
        cp16(sW + (unsigned)(row * pitch + kc) * 2, Wg + (size_t)(n0 + row) * Kp + kc);
    }
    cp_commit();
    asm volatile("cp.async.wait_group 0;");
    __syncthreads();

    int nk   = Kp >> 5;
    int crow = tid >> 2;
    int cko  = (tid & 3) * 8;
    int jbase = n0 >> 2;

    for (int t = t0; t < t1; t++) {
        const __half* hsrc = t ? xout + (size_t)(t - 1) * BB * Kp : h0f;
        const float*  cin  = t ? cbuf + (size_t)((t - 1) & 1) * BB * HH : c0;
        float*  cout = cbuf + (size_t)(t & 1) * BB * HH;
        __half* yout = xout + (size_t)t * BB * Kp;
        const __half* xp = xproj + (size_t)t * BB * N4p;

        uint2 xr[2];
        #pragma unroll
        for (int s = 0; s < 2; s++) {
            int p  = tid + s * 256;
            int b  = p >> 3;
            int jl = p & 7;
            xr[s] = *reinterpret_cast<const uint2*>(
                xp + (size_t)(b0 + b) * N4p + n0 + jl * 4);
        }

        float acc[2][4] = {};

#define ISSUE_H(grp, stage) do {                                           \
        cp16(sH + (unsigned)(stage) * 5120u + (crow * 40 + cko) * 2,       \
             hsrc + (size_t)(b0 + crow) * Kp + ((grp) << 5) + cko);        \
        cp_commit();                                                       \
    } while (0)

        ISSUE_H(0, 0); ISSUE_H(1, 1); ISSUE_H(2, 2);
        ISSUE_H(3, 3); ISSUE_H(4, 4);

        for (int it = 0; it < nk; it++) {
            if (it + 5 <= nk) asm volatile("cp.async.wait_group 4;");
            else              asm volatile("cp.async.wait_group 0;");
            __syncthreads();
            if (it + 5 < nk) { int st = (it + 5) % 6; ISSUE_H(it + 5, st); }

            unsigned ab = sH + (unsigned)(it % 6) * 5120u;
            int k0 = it << 5;
            #pragma unroll
            for (int kk = 0; kk < 32; kk += 16) {
                unsigned af[4], bf[2][2];
                {
                    int ar = wm * 16;
                    ldsm_x4(af[0], af[1], af[2], af[3],
                            ab + (unsigned)(((ar + a_row) * 40 + kk + a_col) * 2));
                }
                {
                    int br = wn * 16;
                    ldsm_x4(bf[0][0], bf[0][1], bf[1][0], bf[1][1],
                            sW + (unsigned)(((br + b_row) * pitch + k0 + kk + b_col) * 2));
                }
                #pragma unroll
                for (int j = 0; j < 2; j++)
                    mma_f16(acc[j], af[0], af[1], af[2], af[3],
                            bf[j][0], bf[j][1]);
            }
        }
#undef ISSUE_H

        int g  = lane >> 2, tg = lane & 3;
        {
            int r0 = wm * 16 + g;
            #pragma unroll
            for (int j = 0; j < 2; j++) {
                int col = wn * 16 + j * 8 + 2 * tg;
                gates[r0 * 33 + col]           = acc[j][0];
                gates[r0 * 33 + col + 1]       = acc[j][1];
                gates[(r0 + 8) * 33 + col]     = acc[j][2];
                gates[(r0 + 8) * 33 + col + 1] = acc[j][3];
            }
        }
        __syncthreads();

        #pragma unroll
        for (int s = 0; s < 2; s++) {
            int p  = tid + s * 256;
            int b  = p >> 3;
            int jl = p & 7;
            int j  = jbase + jl;
            if (j < nh) {
                int bg = b0 + b;
                __half2 x01 = *reinterpret_cast<__half2*>(&xr[s].x);
                __half2 x23 = *reinterpret_cast<__half2*>(&xr[s].y);
                float2 f01 = __half22float2(x01);
                float2 f23 = __half22float2(x23);
                float gi = gates[b * 33 + jl * 4 + 0] + f01.x;
                float gf = gates[b * 33 + jl * 4 + 1] + f01.y;
                float gg = gates[b * 33 + jl * 4 + 2] + f23.x;
                float go = gates[b * 33 + jl * 4 + 3] + f23.y;
                float iv = fsigmoid(gi);
                float fv = fsigmoid(gf);
                float gv = ftanh(gg);
                float ov = fsigmoid(go);
                float cv = fv * cin[(size_t)bg * nh + j] + iv * gv;
                float hv = ov * ftanh(cv);
                cout[(size_t)bg * nh + j] = cv;
                yout[(size_t)bg * Kp + j] = __float2half(hv);
            }
        }

        if (t + 1 < t1) grid_bar(nblocks, blockIdx.y);
    }
}

// ---------------------------------------------------------------------------
// Host-side helpers
// ---------------------------------------------------------------------------
static void prep_layer(cudaStream_t st,
                       const float* W_ih, const float* W_hh,
                       const float* b_ih, const float* b_hh, const float* h0,
                       __half* Wih, __half* Whh, float* bias, __half* h0f,
                       int nh, int K_in, int Kp_in, int Kp_h, int N4p)
{
    reorder_f16<<<N4p, 256, 0, st>>>(W_ih, Wih, nh, K_in, Kp_in);
    reorder_f16<<<N4p, 256, 0, st>>>(W_hh, Whh, nh, nh, Kp_h);
    combine_bias<<<(N4p + 255) / 256, 256, 0, st>>>(b_ih, b_hh, bias, nh, N4p);
    conv_h0<<<BB, 256, 0, st>>>(h0, h0f, nh, Kp_h);
}

static void run_proj(const __half* x_in, const __half* Wih, const float* bias,
                     __half* xproj, int N4p, int Kp_in)
{
    dim3 grid(N4p / 128, (TT * BB) / 128);
    gemm_f16<<<grid, 256, 110592>>>(x_in, Wih, bias, xproj, 1, N4p, Kp_in,
                                    Kp_in, Kp_in, N4p);
}

static void run_rec(const __half* h0f, const float* c0, const __half* Whh,
                    const __half* xproj, float* cbuf, __half* x_out,
                    int nh, int Kp_h, int N4p, int t0, int t1)
{
    int pitch = Kp_h + 8;
    size_t smem = (size_t)32 * pitch * 2 + 6 * 2560 * 2 + 64 * 33 * 4;
    dim3 grid(N4p / 32, 2);
    unsigned nb = N4p / 32;
    lstm_persist32<<<grid, 256, smem>>>(h0f, c0, Whh, xproj, cbuf, x_out,
                                        nh, Kp_h, N4p, pitch, nb, t0, t1);
}

extern "C" void kernel_launch(void* const* d_in, const int* in_sizes, int n_in,
                              void* d_out, int out_size)
{
    const int*   tokens = (const int*)  d_in[0];
    const float* h0_0   = (const float*)d_in[1];
    const float* c0_0   = (const float*)d_in[2];
    const float* h0_1   = (const float*)d_in[3];
    const float* c0_1   = (const float*)d_in[4];
    const float* h0_2   = (const float*)d_in[5];
    const float* c0_2   = (const float*)d_in[6];
    const float* embw   = (const float*)d_in[7];
    const float* W_ih0  = (const float*)d_in[8];
    const float* W_hh0  = (const float*)d_in[9];
    const float* b_ih0  = (const float*)d_in[10];
    const float* b_hh0  = (const float*)d_in[11];
    const float* W_ih1  = (const float*)d_in[12];
    const float* W_hh1  = (const float*)d_in[13];
    const float* b_ih1  = (const float*)d_in[14];
    const float* b_hh1  = (const float*)d_in[15];
    const float* W_ih2  = (const float*)d_in[16];
    const float* W_hh2  = (const float*)d_in[17];
    const float* b_ih2  = (const float*)d_in[18];
    const float* b_hh2  = (const float*)d_in[19];
    const float* dec_b  = (const float*)d_in[20];
    float* logits = (float*)d_out;

    __half *x0, *x1, *x2, *x3, *embf, *xproj, *h0f0, *h0f1, *h0f2;
    __half *Wih0, *Whh0, *Wih1, *Whh1, *Wih2, *Whh2;
    float *bias0, *bias1, *bias2, *cbuf;
    cudaGetSymbolAddress((void**)&x0,    g_x0);
    cudaGetSymbolAddress((void**)&x1,    g_x1);
    cudaGetSymbolAddress((void**)&x2,    g_x2);
    cudaGetSymbolAddress((void**)&x3,    g_x3);
    cudaGetSymbolAddress((void**)&embf,  g_embf);
    cudaGetSymbolAddress((void**)&Wih0,  g_Wih0);
    cudaGetSymbolAddress((void**)&Whh0,  g_Whh0);
    cudaGetSymbolAddress((void**)&Wih1,  g_Wih1);
    cudaGetSymbolAddress((void**)&Whh1,  g_Whh1);
    cudaGetSymbolAddress((void**)&Wih2,  g_Wih2);
    cudaGetSymbolAddress((void**)&Whh2,  g_Whh2);
    cudaGetSymbolAddress((void**)&bias0, g_bias0);
    cudaGetSymbolAddress((void**)&bias1, g_bias1);
    cudaGetSymbolAddress((void**)&bias2, g_bias2);
    cudaGetSymbolAddress((void**)&h0f0,  g_h0f0);
    cudaGetSymbolAddress((void**)&h0f1,  g_h0f1);
    cudaGetSymbolAddress((void**)&h0f2,  g_h0f2);
    cudaGetSymbolAddress((void**)&xproj, g_xproj);
    cudaGetSymbolAddress((void**)&cbuf,  g_c);

    cudaFuncSetAttribute(gemm_f16, cudaFuncAttributeMaxDynamicSharedMemorySize,
                         110592);
    cudaFuncSetAttribute(lstm_persist32,
                         cudaFuncAttributeMaxDynamicSharedMemorySize,
                         32 * (KP_H + 8) * 2 + 6 * 2560 * 2 + 64 * 33 * 4);

    // One-time stream/event resources (identical work every call)
    static cudaStream_t s_side = 0;
    static cudaEvent_t eFork = 0, ePrep = 0, eMid = 0, eDec = 0;
    if (!s_side) {
        cudaStreamCreateWithFlags(&s_side, cudaStreamNonBlocking);
        cudaEventCreateWithFlags(&eFork, cudaEventDisableTiming);
        cudaEventCreateWithFlags(&ePrep, cudaEventDisableTiming);
        cudaEventCreateWithFlags(&eMid,  cudaEventDisableTiming);
        cudaEventCreateWithFlags(&eDec,  cudaEventDisableTiming);
    }

    // Fork: side branch does decoder-table conversion + layer-1/2 prep.
    cudaEventRecord(eFork, 0);
    cudaStreamWaitEvent(s_side, eFork, 0);

    conv_emb<<<VV, 128, 0, s_side>>>(embw, embf);
    prep_layer(s_side, W_ih1, W_hh1, b_ih1, b_hh1, h0_1,
               Wih1, Whh1, bias1, h0f1, HH, HH, KP_H, KP_H, N4P_H);
    prep_layer(s_side, W_ih2, W_hh2, b_ih2, b_hh2, h0_2,
               Wih2, Whh2, bias2, h0f2, EE, HH, KP_H, KP_E, N4P_E);
    cudaEventRecord(ePrep, s_side);

    // Main branch: layer 0
    prep_layer(0, W_ih0, W_hh0, b_ih0, b_hh0, h0_0,
               Wih0, Whh0, bias0, h0f0, HH, EE, KP_E, KP_H, N4P_H);
    embed_f16<<<TT * BB, 256>>>(tokens, embw, x0);
    run_proj(x0, Wih0, bias0, xproj, N4P_H, KP_E);
    run_rec(h0f0, c0_0, Whh0, xproj, cbuf, x1, HH, KP_H, N4P_H, 0, TT);

    // Join side prep; layers 1 and 2
    cudaStreamWaitEvent(0, ePrep, 0);
    run_proj(x1, Wih1, bias1, xproj, N4P_H, KP_H);
    run_rec(h0f1, c0_1, Whh1, xproj, cbuf, x2, HH, KP_H, N4P_H, 0, TT);

    run_proj(x2, Wih2, bias2, xproj, N4P_E, KP_H);
    run_rec(h0f2, c0_2, Whh2, xproj, cbuf, x3, EE, KP_E, N4P_E, 0, 35);
    cudaEventRecord(eMid, 0);

    // Main branch: recurrence part 2 (enqueued first for priority)
    run_rec(h0f2, c0_2, Whh2, xproj, cbuf, x3, EE, KP_E, N4P_E, 35, TT);

    // Side branch: decoder chunk 1 (rows t<35) concurrent with rec part 2
    cudaStreamWaitEvent(s_side, eMid, 0);
    {
        dim3 grid((VV + 127) / 128, 35);
        gemm_f16<<<grid, 256, 110592, s_side>>>(x3, embf, dec_b, logits, 0,
                                                VV, KP_E, KP_E, KP_E, VV);
    }
    cudaEventRecord(eDec, s_side);

    // Main branch: decoder chunk 2 (rows t>=35), then join
    {
        dim3 grid((VV + 127) / 128, 35);
        gemm_f16<<<grid, 256, 110592>>>(x3 + (size_t)4480 * KP_E, embf, dec_b,
                                        logits + (size_t)4480 * VV, 0,
                                        VV, KP_E, KP_E, KP_E, VV);
    }
    cudaStreamWaitEvent(0, eDec, 0);
}

// round 16
// speedup vs baseline: 1.3700x; 1.0076x over previous
#include <cuda_runtime.h>
#include <cuda_fp16.h>
#include <math.h>
#include <stdint.h>

// Problem constants
#define TT 70
#define BB 128
#define EE 400
#define HH 1150
#define VV 33278

// Padded dims (K multiples of 64 for GEMM BK; strides 16B-aligned)
#define KP_E 448
#define KP_H 1152
#define N4P_H 4608
#define N4P_E 1664

// ---------------------------------------------------------------------------
// Scratch (device globals; zero-initialized at module load)
// ---------------------------------------------------------------------------
__device__ __half g_x0  [TT * BB * KP_E];
__device__ __half g_x1  [TT * BB * KP_H];
__device__ __half g_x2  [TT * BB * KP_H];
__device__ __half g_x3  [TT * BB * KP_E];
__device__ __half g_embf[VV * KP_E];
__device__ __half g_Wih0[N4P_H * KP_E];
__device__ __half g_Whh0[N4P_H * KP_H];
__device__ __half g_Wih1[N4P_H * KP_H];
__device__ __half g_Whh1[N4P_H * KP_H];
__device__ __half g_Wih2[N4P_E * KP_H];
__device__ __half g_Whh2[N4P_E * KP_E];
__device__ float  g_bias0[N4P_H];
__device__ float  g_bias1[N4P_H];
__device__ float  g_bias2[N4P_E];
__device__ __half g_h0f0[BB * KP_H];
__device__ __half g_h0f1[BB * KP_H];
__device__ __half g_h0f2[BB * KP_E];
__device__ __half g_xproj[TT * BB * N4P_H];   // fp16 x-projection
__device__ float  g_c   [2 * BB * HH];
__device__ unsigned g_count[2];               // per-batch-half barrier counters
__device__ volatile unsigned g_gen[2];        // per-batch-half generations

// ---------------------------------------------------------------------------
// PTX helpers
// ---------------------------------------------------------------------------
__device__ __forceinline__ void cp16(unsigned s, const void* g) {
    asm volatile("cp.async.cg.shared.global [%0], [%1], 16;" :: "r"(s), "l"(g));
}
__device__ __forceinline__ void cp16z(unsigned s, const void* g, int sz) {
    asm volatile("cp.async.cg.shared.global [%0], [%1], 16, %2;" :: "r"(s), "l"(g), "r"(sz));
}
__device__ __forceinline__ void cp_commit() {
    asm volatile("cp.async.commit_group;");
}
__device__ __forceinline__ void mma_f16(float c[4], unsigned a0, unsigned a1,
                                        unsigned a2, unsigned a3,
                                        unsigned b0, unsigned b1)
{
    asm("mma.sync.aligned.m16n8k16.row.col.f32.f16.f16.f32 "
        "{%0,%1,%2,%3},{%4,%5,%6,%7},{%8,%9},{%0,%1,%2,%3};"
        : "+f"(c[0]), "+f"(c[1]), "+f"(c[2]), "+f"(c[3])
        : "r"(a0), "r"(a1), "r"(a2), "r"(a3), "r"(b0), "r"(b1));
}
__device__ __forceinline__ void ldsm_x4(unsigned& r0, unsigned& r1,
                                        unsigned& r2, unsigned& r3, uint32_t a)
{
    asm volatile("ldmatrix.sync.aligned.m8n8.x4.shared.b16 {%0,%1,%2,%3}, [%4];"
                 : "=r"(r0), "=r"(r1), "=r"(r2), "=r"(r3) : "r"(a));
}
__device__ __forceinline__ float fsigmoid(float x) {
    return 1.0f / (1.0f + __expf(-x));
}
__device__ __forceinline__ float ftanh(float x) {
    return 2.0f / (1.0f + __expf(-2.0f * x)) - 1.0f;
}

// Per-half grid barrier
__device__ __forceinline__ void grid_bar(unsigned nblocks, int idx) {
    __syncthreads();
    if (threadIdx.x == 0) {
        unsigned old = g_gen[idx];
        __threadfence();
        unsigned t = atomicAdd(&g_count[idx], 1u);
        if (t == nblocks - 1u) {
            g_count[idx] = 0u;
            __threadfence();
            g_gen[idx] = old + 1u;
        } else {
            while (g_gen[idx] == old) { }
        }
        __threadfence();
    }
    __syncthreads();
}

// ---------------------------------------------------------------------------
// Preprocessing kernels (vectorized)
// ---------------------------------------------------------------------------
__global__ void embed_f16(const int* __restrict__ tokens,
                          const float* __restrict__ emb,
                          __half* __restrict__ out)
{
    int tb = blockIdx.x;
    int tok = tokens[tb];
    const float2* src = (const float2*)(emb + (size_t)tok * EE);
    __half2* dst = (__half2*)(out + (size_t)tb * KP_E);
    for (int e = threadIdx.x; e < KP_E / 2; e += blockDim.x) {
        float2 v = (2 * e < EE) ? src[e] : make_float2(0.f, 0.f);
        dst[e] = __floats2half2_rn(v.x, v.y);
    }
}

__global__ void conv_emb(const float* __restrict__ emb, __half* __restrict__ out)
{
    int row = blockIdx.x;
    const float2* src = (const float2*)(emb + (size_t)row * EE);
    __half2* dst = (__half2*)(out + (size_t)row * KP_E);
    for (int e = threadIdx.x; e < KP_E / 2; e += blockDim.x) {
        float2 v = (2 * e < EE) ? src[e] : make_float2(0.f, 0.f);
        dst[e] = __floats2half2_rn(v.x, v.y);
    }
}

__global__ void reorder_f16(const float* __restrict__ W, __half* __restrict__ Wr,
                            int nh, int K, int Kp)
{
    int row = blockIdx.x;
    int j = row >> 2, g = row & 3;
    bool valid = (row < 4 * nh);
    const float2* src = (const float2*)(W + (size_t)(g * nh + j) * K);
    __half2* dst = (__half2*)(Wr + (size_t)row * Kp);
    for (int k = threadIdx.x; k < Kp / 2; k += blockDim.x) {
        float2 v = (valid && 2 * k < K) ? src[k] : make_float2(0.f, 0.f);
        dst[k] = __floats2half2_rn(v.x, v.y);
    }
}

__global__ void combine_bias(const float* __restrict__ b1, const float* __restrict__ b2,
                             float* __restrict__ br, int nh, int N4p)
{
    int r = blockIdx.x * blockDim.x + threadIdx.x;
    if (r < N4p) {
        int j = r >> 2, g = r & 3;
        br[r] = (r < 4 * nh) ? b1[g * nh + j] + b2[g * nh + j] : 0.0f;
    }
}

__global__ void conv_h0(const float* __restrict__ h0, __half* __restrict__ out,
                        int nh, int Kp)
{
    int b = blockIdx.x;
    const float2* src = (const float2*)(h0 + (size_t)b * nh);
    __half2* dst = (__half2*)(out + (size_t)b * Kp);
    for (int k = threadIdx.x; k < Kp / 2; k += blockDim.x) {
        float2 v = (2 * k < nh) ? src[k] : make_float2(0.f, 0.f);
        dst[k] = __floats2half2_rn(v.x, v.y);
    }
}

// ---------------------------------------------------------------------------
// FP16 GEMM (NT), BK=64, 3-stage cp.async pipeline + ldmatrix, 2 CTAs/SM.
// C[m,n] = sum_{k<Kreal} A[m,k]*B[n,k] + bias[n]; out_half selects C dtype.
// Partial-K: last iteration computes only ceil((Kreal - it*64)/16)*16 cols.
// Buffers must be zero-padded to a 64-multiple >= Kreal (lda/ldb stride).
// Block 128x128, 256 threads (8 warps 2m x 4n), warp tile 64x32.
// ---------------------------------------------------------------------------
__global__ void __launch_bounds__(256, 2) gemm_f16(
    const __half* __restrict__ A, const __half* __restrict__ B,
    const float* __restrict__ bias, void* __restrict__ Cv, int out_half,
    int N, int Kreal, int lda, int ldb, int ldc)
{
    extern __shared__ __align__(16) char dsm[];
    unsigned sA = (unsigned)__cvta_generic_to_shared(dsm);        // 3 x 18432 B
    unsigned sB = sA + 3u * 18432u;                               // 3 x 18432 B

    int tid  = threadIdx.x;
    int warp = tid >> 5, lane = tid & 31;
    int wm = warp & 1, wn = warp >> 1;
    int g  = lane >> 2, tg = lane & 3;
    int m0 = blockIdx.y * 128;
    int n0 = blockIdx.x * 128;

    int a_row = (lane & 7) + ((lane >> 3) & 1) * 8;
    int a_col = (lane >> 4) * 8;
    int b_row = (lane & 7) + (lane >> 4) * 8;
    int b_col = ((lane >> 3) & 1) * 8;

    int crow[4], cko[4];
    #pragma unroll
    for (int s = 0; s < 4; s++) {
        int c = tid + s * 256;
        crow[s] = c >> 3;
        cko[s]  = (c & 7) * 8;
    }

    float acc[4][4][4] = {};
    int nk = (Kreal + 63) >> 6;      // 7 (K=400) or 18 (K=1152)

#define ISSUE_AB(grp, stage) do {                                              \
        int _kt = (grp) << 6;                                                  \
        unsigned _so = (unsigned)(stage) * 18432u;                             \
        _Pragma("unroll")                                                      \
        for (int s = 0; s < 4; s++) {                                          \
            int row = crow[s], ko = cko[s];                                    \
            cp16(sA + _so + (unsigned)((row * 72 + ko) * 2),                   \
                 A + (size_t)(m0 + row) * lda + _kt + ko);                     \
            int gn = n0 + row;                                                 \
            int sz = (gn < N) ? 16 : 0;                                        \
            const __half* gb = B + (size_t)(gn < N ? gn : 0) * ldb + _kt + ko; \
            cp16z(sB + _so + (unsigned)((row * 72 + ko) * 2), gb, sz);         \
        }                                                                      \
        cp_commit();                                                           \
    } while (0)

    ISSUE_AB(0, 0);
    ISSUE_AB(1, 1);

    for (int it = 0; it < nk; it++) {
        if (it + 2 <= nk) asm volatile("cp.async.wait_group 1;");
        else              asm volatile("cp.async.wait_group 0;");
        __syncthreads();
        if (it + 2 < nk) { int st = (it + 2) % 3; ISSUE_AB(it + 2, st); }

        unsigned ab = sA + (unsigned)(it % 3) * 18432u;
        unsigned bb = sB + (unsigned)(it % 3) * 18432u;
        int kmax = Kreal - (it << 6);     // cols remaining (uniform per CTA)
        #pragma unroll
        for (int kk = 0; kk < 64; kk += 16) {
            if (kk < kmax) {
                unsigned af[4][4], bf[4][2];
                #pragma unroll
                for (int i = 0; i < 4; i++) {
                    int ar = wm * 64 + i * 16;
                    ldsm_x4(af[i][0], af[i][1], af[i][2], af[i][3],
                            ab + (unsigned)(((ar + a_row) * 72 + kk + a_col) * 2));
                }
                #pragma unroll
                for (int j = 0; j < 4; j += 2) {
                    int br = wn * 32 + j * 8;
                    ldsm_x4(bf[j][0], bf[j][1], bf[j + 1][0], bf[j + 1][1],
                            bb + (unsigned)(((br + b_row) * 72 + kk + b_col) * 2));
                }
                #pragma unroll
                for (int i = 0; i < 4; i++)
                    #pragma unroll
                    for (int j = 0; j < 4; j++)
                        mma_f16(acc[i][j], af[i][0], af[i][1], af[i][2], af[i][3],
                                bf[j][0], bf[j][1]);
            }
        }
    }
#undef ISSUE_AB

    #pragma unroll
    for (int i = 0; i < 4; i++) {
        int r0 = m0 + wm * 64 + i * 16 + g;
        #pragma unroll
        for (int j = 0; j < 4; j++) {
            int col = n0 + wn * 32 + j * 8 + 2 * tg;
            if (col < N) {
                float bz  = bias ? bias[col] : 0.0f;
                float bz1 = bias ? bias[col + 1] : 0.0f;
                float v00 = acc[i][j][0] + bz, v01 = acc[i][j][1] + bz1;
                float v10 = acc[i][j][2] + bz, v11 = acc[i][j][3] + bz1;
                if (out_half) {
                    __half* Ch = (__half*)Cv;
                    *reinterpret_cast<__half2*>(Ch + (size_t)r0 * ldc + col) =
                        __floats2half2_rn(v00, v01);
                    *reinterpret_cast<__half2*>(Ch + (size_t)(r0 + 8) * ldc + col) =
                        __floats2half2_rn(v10, v11);
                } else {
                    float* Cf = (float*)Cv;
                    float2 a = {v00, v01}, b = {v10, v11};
                    *reinterpret_cast<float2*>(Cf + (size_t)r0 * ldc + col) = a;
                    *reinterpret_cast<float2*>(Cf + (size_t)(r0 + 8) * ldc + col) = b;
                }
            }
        }
    }
}

// ---------------------------------------------------------------------------
// Persistent LSTM recurrence, NTILE=32 tile, 2 CTAs/SM, steps [t0, t1).
// xp is fp16; per-batch-half grid barrier. (BK=32 — loop is latency-bound.)
// ---------------------------------------------------------------------------
__global__ void __launch_bounds__(256, 2) lstm_persist32(
    const __half* __restrict__ h0f,
    const float*  __restrict__ c0,
    const __half* __restrict__ Wg,
    const __half* __restrict__ xproj,
    float* __restrict__ cbuf,
    __half* __restrict__ xout,
    int nh, int Kp, int N4p, int pitch, unsigned nblocks, int t0, int t1)
{
    extern __shared__ __align__(16) char dsm[];
    __half* Ws   = (__half*)dsm;                      // 32 x pitch
    __half* Hs   = Ws + 32 * pitch;                   // 6 stages x 2560
    float*  gates = (float*)(Hs + 6 * 2560);          // 64 x 33

    int tid  = threadIdx.x;
    int warp = tid >> 5, lane = tid & 31;
    int wm = warp >> 1;
    int wn = warp & 1;
    int n0 = blockIdx.x * 32;
    int b0 = blockIdx.y * 64;

    unsigned sW = (unsigned)__cvta_generic_to_shared(Ws);
    unsigned sH = (unsigned)__cvta_generic_to_shared(Hs);

    int a_row = (lane & 7) + ((lane >> 3) & 1) * 8;
    int a_col = (lane >> 4) * 8;
    int b_row = (lane & 7) + (lane >> 4) * 8;
    int b_col = ((lane >> 3) & 1) * 8;

    int kch = Kp >> 3;
    for (int c = tid; c < 32 * kch; c += 256) {
        int row = c / kch;
        int kc  = (c - row * kch) << 3;
        cp16(sW + (unsigned)(row * pitch + kc) * 2, Wg + (size_t)(n0 + row) * Kp + kc);
    }
    cp_commit();
    asm volatile("cp.async.wait_group 0;");
    __syncthreads();

    int nk   = Kp >> 5;
    int crow = tid >> 2;
    int cko  = (tid & 3) * 8;
    int jbase = n0 >> 2;

    for (int t = t0; t < t1; t++) {
        const __half* hsrc = t ? xout + (size_t)(t - 1) * BB * Kp : h0f;
        const float*  cin  = t ? cbuf + (size_t)((t - 1) & 1) * BB * HH : c0;
        float*  cout = cbuf + (size_t)(t & 1) * BB * HH;
        __half* yout = xout + (size_t)t * BB * Kp;
        const __half* xp = xproj + (size_t)t * BB * N4p;

        uint2 xr[2];
        #pragma unroll
        for (int s = 0; s < 2; s++) {
            int p  = tid + s * 256;
            int b  = p >> 3;
            int jl = p & 7;
            xr[s] = *reinterpret_cast<const uint2*>(
                xp + (size_t)(b0 + b) * N4p + n0 + jl * 4);
        }

        float acc[2][4] = {};

#define ISSUE_H(grp, stage) do {                                           \
        cp16(sH + (unsigned)(stage) * 5120u + (crow * 40 + cko) * 2,       \
             hsrc + (size_t)(b0 + crow) * Kp + ((grp) << 5) + cko);        \
        cp_commit();                                                       \
    } while (0)

        ISSUE_H(0, 0); ISSUE_H(1, 1); ISSUE_H(2, 2);
        ISSUE_H(3, 3); ISSUE_H(4, 4);

        for (int it = 0; it < nk; it++) {
            if (it + 5 <= nk) asm volatile("cp.async.wait_group 4;");
            else              asm volatile("cp.async.wait_group 0;");
            __syncthreads();
            if (it + 5 < nk) { int st = (it + 5) % 6; ISSUE_H(it + 5, st); }

            unsigned ab = sH + (unsigned)(it % 6) * 5120u;
            int k0 = it << 5;
            #pragma unroll
            for (int kk = 0; kk < 32; kk += 16) {
                unsigned af[4], bf[2][2];
                {
                    int ar = wm * 16;
                    ldsm_x4(af[0], af[1], af[2], af[3],
                            ab + (unsigned)(((ar + a_row) * 40 + kk + a_col) * 2));
                }
                {
                    int br = wn * 16;
                    ldsm_x4(bf[0][0], bf[0][1], bf[1][0], bf[1][1],
                            sW + (unsigned)(((br + b_row) * pitch + k0 + kk + b_col) * 2));
                }
                #pragma unroll
                for (int j = 0; j < 2; j++)
                    mma_f16(acc[j], af[0], af[1], af[2], af[3],
                            bf[j][0], bf[j][1]);
            }
        }
#undef ISSUE_H

        int g  = lane >> 2, tg = lane & 3;
        {
            int r0 = wm * 16 + g;
            #pragma unroll
            for (int j = 0; j < 2; j++) {
                int col = wn * 16 + j * 8 + 2 * tg;
                gates[r0 * 33 + col]           = acc[j][0];
                gates[r0 * 33 + col + 1]       = acc[j][1];
                gates[(r0 + 8) * 33 + col]     = acc[j][2];
                gates[(r0 + 8) * 33 + col + 1] = acc[j][3];
            }
        }
        __syncthreads();

        #pragma unroll
        for (int s = 0; s < 2; s++) {
            int p  = tid + s * 256;
            int b  = p >> 3;
            int jl = p & 7;
            int j  = jbase + jl;
            if (j < nh) {
                int bg = b0 + b;
                __half2 x01 = *reinterpret_cast<__half2*>(&xr[s].x);
                __half2 x23 = *reinterpret_cast<__half2*>(&xr[s].y);
                float2 f01 = __half22float2(x01);
                float2 f23 = __half22float2(x23);
                float gi = gates[b * 33 + jl * 4 + 0] + f01.x;
                float gf = gates[b * 33 + jl * 4 + 1] + f01.y;
                float gg = gates[b * 33 + jl * 4 + 2] + f23.x;
                float go = gates[b * 33 + jl * 4 + 3] + f23.y;
                float iv = fsigmoid(gi);
                float fv = fsigmoid(gf);
                float gv = ftanh(gg);
                float ov = fsigmoid(go);
                float cv = fv * cin[(size_t)bg * nh + j] + iv * gv;
                float hv = ov * ftanh(cv);
                cout[(size_t)bg * nh + j] = cv;
                yout[(size_t)bg * Kp + j] = __float2half(hv);
            }
        }

        if (t + 1 < t1) grid_bar(nblocks, blockIdx.y);
    }
}

// ---------------------------------------------------------------------------
// Host-side helpers
// ---------------------------------------------------------------------------
static void prep_layer(cudaStream_t st,
                       const float* W_ih, const float* W_hh,
                       const float* b_ih, const float* b_hh, const float* h0,
                       __half* Wih, __half* Whh, float* bias, __half* h0f,
                       int nh, int K_in, int Kp_in, int Kp_h, int N4p)
{
    reorder_f16<<<N4p, 256, 0, st>>>(W_ih, Wih, nh, K_in, Kp_in);
    reorder_f16<<<N4p, 256, 0, st>>>(W_hh, Whh, nh, nh, Kp_h);
    combine_bias<<<(N4p + 255) / 256, 256, 0, st>>>(b_ih, b_hh, bias, nh, N4p);
    conv_h0<<<BB, 256, 0, st>>>(h0, h0f, nh, Kp_h);
}

static void run_proj(const __half* x_in, const __half* Wih, const float* bias,
                     __half* xproj, int N4p, int Kreal, int Kp_in)
{
    dim3 grid(N4p / 128, (TT * BB) / 128);
    gemm_f16<<<grid, 256, 110592>>>(x_in, Wih, bias, xproj, 1, N4p, Kreal,
                                    Kp_in, Kp_in, N4p);
}

static void run_rec(const __half* h0f, const float* c0, const __half* Whh,
                    const __half* xproj, float* cbuf, __half* x_out,
                    int nh, int Kp_h, int N4p, int t0, int t1)
{
    int pitch = Kp_h + 8;
    size_t smem = (size_t)32 * pitch * 2 + 6 * 2560 * 2 + 64 * 33 * 4;
    dim3 grid(N4p / 32, 2);
    unsigned nb = N4p / 32;
    lstm_persist32<<<grid, 256, smem>>>(h0f, c0, Whh, xproj, cbuf, x_out,
                                        nh, Kp_h, N4p, pitch, nb, t0, t1);
}

extern "C" void kernel_launch(void* const* d_in, const int* in_sizes, int n_in,
                              void* d_out, int out_size)
{
    const int*   tokens = (const int*)  d_in[0];
    const float* h0_0   = (const float*)d_in[1];
    const float* c0_0   = (const float*)d_in[2];
    const float* h0_1   = (const float*)d_in[3];
    const float* c0_1   = (const float*)d_in[4];
    const float* h0_2   = (const float*)d_in[5];
    const float* c0_2   = (const float*)d_in[6];
    const float* embw   = (const float*)d_in[7];
    const float* W_ih0  = (const float*)d_in[8];
    const float* W_hh0  = (const float*)d_in[9];
    const float* b_ih0  = (const float*)d_in[10];
    const float* b_hh0  = (const float*)d_in[11];
    const float* W_ih1  = (const float*)d_in[12];
    const float* W_hh1  = (const float*)d_in[13];
    const float* b_ih1  = (const float*)d_in[14];
    const float* b_hh1  = (const float*)d_in[15];
    const float* W_ih2  = (const float*)d_in[16];
    const float* W_hh2  = (const float*)d_in[17];
    const float* b_ih2  = (const float*)d_in[18];
    const float* b_hh2  = (const float*)d_in[19];
    const float* dec_b  = (const float*)d_in[20];
    float* logits = (float*)d_out;

    __half *x0, *x1, *x2, *x3, *embf, *xproj, *h0f0, *h0f1, *h0f2;
    __half *Wih0, *Whh0, *Wih1, *Whh1, *Wih2, *Whh2;
    float *bias0, *bias1, *bias2, *cbuf;
    cudaGetSymbolAddress((void**)&x0,    g_x0);
    cudaGetSymbolAddress((void**)&x1,    g_x1);
    cudaGetSymbolAddress((void**)&x2,    g_x2);
    cudaGetSymbolAddress((void**)&x3,    g_x3);
    cudaGetSymbolAddress((void**)&embf,  g_embf);
    cudaGetSymbolAddress((void**)&Wih0,  g_Wih0);
    cudaGetSymbolAddress((void**)&Whh0,  g_Whh0);
    cudaGetSymbolAddress((void**)&Wih1,  g_Wih1);
    cudaGetSymbolAddress((void**)&Whh1,  g_Whh1);
    cudaGetSymbolAddress((void**)&Wih2,  g_Wih2);
    cudaGetSymbolAddress((void**)&Whh2,  g_Whh2);
    cudaGetSymbolAddress((void**)&bias0, g_bias0);
    cudaGetSymbolAddress((void**)&bias1, g_bias1);
    cudaGetSymbolAddress((void**)&bias2, g_bias2);
    cudaGetSymbolAddress((void**)&h0f0,  g_h0f0);
    cudaGetSymbolAddress((void**)&h0f1,  g_h0f1);
    cudaGetSymbolAddress((void**)&h0f2,  g_h0f2);
    cudaGetSymbolAddress((void**)&xproj, g_xproj);
    cudaGetSymbolAddress((void**)&cbuf,  g_c);

    cudaFuncSetAttribute(gemm_f16, cudaFuncAttributeMaxDynamicSharedMemorySize,
                         110592);
    cudaFuncSetAttribute(lstm_persist32,
                         cudaFuncAttributeMaxDynamicSharedMemorySize,
                         32 * (KP_H + 8) * 2 + 6 * 2560 * 2 + 64 * 33 * 4);

    // One-time stream/event resources (identical work every call)
    static cudaStream_t s_side = 0;
    static cudaEvent_t eFork = 0, ePrep = 0, eMid = 0, eDec = 0;
    if (!s_side) {
        cudaStreamCreateWithFlags(&s_side, cudaStreamNonBlocking);
        cudaEventCreateWithFlags(&eFork, cudaEventDisableTiming);
        cudaEventCreateWithFlags(&ePrep, cudaEventDisableTiming);
        cudaEventCreateWithFlags(&eMid,  cudaEventDisableTiming);
        cudaEventCreateWithFlags(&eDec,  cudaEventDisableTiming);
    }

    // Fork: side branch does decoder-table conversion + layer-1/2 prep.
    cudaEventRecord(eFork, 0);
    cudaStreamWaitEvent(s_side, eFork, 0);

    conv_emb<<<VV, 128, 0, s_side>>>(embw, embf);
    prep_layer(s_side, W_ih1, W_hh1, b_ih1, b_hh1, h0_1,
               Wih1, Whh1, bias1, h0f1, HH, HH, KP_H, KP_H, N4P_H);
    prep_layer(s_side, W_ih2, W_hh2, b_ih2, b_hh2, h0_2,
               Wih2, Whh2, bias2, h0f2, EE, HH, KP_H, KP_E, N4P_E);
    cudaEventRecord(ePrep, s_side);

    // Main branch: layer 0
    prep_layer(0, W_ih0, W_hh0, b_ih0, b_hh0, h0_0,
               Wih0, Whh0, bias0, h0f0, HH, EE, KP_E, KP_H, N4P_H);
    embed_f16<<<TT * BB, 256>>>(tokens, embw, x0);
    run_proj(x0, Wih0, bias0, xproj, N4P_H, EE, KP_E);      // Kreal=400
    run_rec(h0f0, c0_0, Whh0, xproj, cbuf, x1, HH, KP_H, N4P_H, 0, TT);

    // Join side prep; layers 1 and 2
    cudaStreamWaitEvent(0, ePrep, 0);
    run_proj(x1, Wih1, bias1, xproj, N4P_H, KP_H, KP_H);    // Kreal=1152
    run_rec(h0f1, c0_1, Whh1, xproj, cbuf, x2, HH, KP_H, N4P_H, 0, TT);

    run_proj(x2, Wih2, bias2, xproj, N4P_E, KP_H, KP_H);    // Kreal=1152
    run_rec(h0f2, c0_2, Whh2, xproj, cbuf, x3, EE, KP_E, N4P_E, 0, 35);
    cudaEventRecord(eMid, 0);

    // Main branch: recurrence part 2 (enqueued first for priority)
    run_rec(h0f2, c0_2, Whh2, xproj, cbuf, x3, EE, KP_E, N4P_E, 35, TT);

    // Side branch: decoder chunk 1 (rows t<35) concurrent with rec part 2
    cudaStreamWaitEvent(s_side, eMid, 0);
    {
        dim3 grid((VV + 127) / 128, 35);
        gemm_f16<<<grid, 256, 110592, s_side>>>(x3, embf, dec_b, logits, 0,
                                                VV, EE, KP_E, KP_E, VV);
    }
    cudaEventRecord(eDec, s_side);

    // Main branch: decoder chunk 2 (rows t>=35), then join
    {
        dim3 grid((VV + 127) / 128, 35);
        gemm_f16<<<grid, 256, 110592>>>(x3 + (size_t)4480 * KP_E, embf, dec_b,
                                        logits + (size_t)4480 * VV, 0,
                                        VV, EE, KP_E, KP_E, VV);
    }
    cudaStreamWaitEvent(0, eDec, 0);
}